// round 7
// baseline (speedup 1.0000x reference)
#include <cuda_runtime.h>
#include <cuda_fp16.h>
#include <math.h>
#include <stdint.h>

// ---------------- problem constants ----------------
#define BATCH 16
#define HW    56
#define CH    384
#define NHEAD 12
#define WS    7
#define NTOK  49
#define HD    32
#define NWIN  64
#define MROWS 50176
#define HID   1536
#define SCALE 0.17677669529663687f

// ---------------- scratch ----------------
__device__ __half g_xg[(long)MROWS * CH];
__device__ __half g_qkv[(long)MROWS * 3 * CH];
__device__ __half g_at[(long)MROWS * CH];
__device__ float  g_x2[(long)MROWS * CH];
__device__ __half g_hn[(long)MROWS * CH];
__device__ __half g_hid[(long)MROWS * HID];
__device__ int    g_map[MROWS];
__device__ __half g_wqkv_hi[3 * CH * CH], g_wqkv_lo[3 * CH * CH];
__device__ __half g_wprj_hi[CH * CH],     g_wprj_lo[CH * CH];
__device__ __half g_wf1_hi[HID * CH],     g_wf1_lo[HID * CH];
__device__ __half g_wf2_hi[CH * HID],     g_wf2_lo[CH * HID];

// ---------------- helpers ----------------
__device__ __forceinline__ uint32_t smem_u32(const void* p) {
    uint32_t a;
    asm("{ .reg .u64 t; cvta.to.shared.u64 t, %1; cvt.u32.u64 %0, t; }" : "=r"(a) : "l"(p));
    return a;
}

#define CP16(dst, src) asm volatile("cp.async.cg.shared.global [%0], [%1], 16;\n" :: "r"(dst), "l"(src))
#define CP_COMMIT()    asm volatile("cp.async.commit_group;\n" ::: "memory")
#define CP_WAIT(n)     asm volatile("cp.async.wait_group %0;\n" :: "n"(n) : "memory")

__device__ __forceinline__ void ldsm4(uint32_t* r, uint32_t addr) {
    asm volatile("ldmatrix.sync.aligned.m8n8.x4.shared.b16 {%0,%1,%2,%3}, [%4];"
                 : "=r"(r[0]), "=r"(r[1]), "=r"(r[2]), "=r"(r[3]) : "r"(addr));
}

__device__ __forceinline__ void mma16816(float* c, const uint32_t* a, uint32_t b0, uint32_t b1) {
    asm volatile(
        "mma.sync.aligned.m16n8k16.row.col.f32.f16.f16.f32 "
        "{%0,%1,%2,%3}, {%4,%5,%6,%7}, {%8,%9}, {%0,%1,%2,%3};\n"
        : "+f"(c[0]), "+f"(c[1]), "+f"(c[2]), "+f"(c[3])
        : "r"(a[0]), "r"(a[1]), "r"(a[2]), "r"(a[3]), "r"(b0), "r"(b1));
}

// ---------------- row permutation map ----------------
__global__ void build_maps_kernel(int* __restrict__ map) {
    int r = blockIdx.x * 256 + threadIdx.x;
    if (r >= MROWS) return;
    int w = r / NTOK, t = r % NTOK;
    int b = w / NWIN, wrem = w % NWIN;
    int wi = wrem / 8, wj = wrem % 8;
    int ti = t / WS, tj = t % WS;
    int h0 = (wi * WS + ti + 3) % HW;
    int w0 = (wj * WS + tj + 3) % HW;
    map[r] = b * (HW * HW) + h0 * HW + w0;
}

// ---------------- conversions ----------------
__device__ __forceinline__ void split_fp16(float v, __half& h, __half& l) {
    h = __float2half(v);
    l = __float2half(v - __half2float(h));
}

__global__ void conv_wsplit(const float* __restrict__ src,
                            __half* __restrict__ hi, __half* __restrict__ lo, long n) {
    long i = (long)blockIdx.x * 256 + threadIdx.x;
    if (i >= n) return;
    __half h, l;
    split_fp16(src[i], h, l);
    hi[i] = h; lo[i] = l;
}

__global__ void conv_gather(const float* __restrict__ x, const int* __restrict__ map,
                            __half* __restrict__ o) {
    long i = (long)blockIdx.x * 256 + threadIdx.x;
    if (i >= (long)MROWS * CH) return;
    long r = i / CH, c = i % CH;
    o[i] = __float2half(x[(long)map[r] * CH + c]);
}

// ---------------- pipelined fp16x2 HMMA GEMM ------------------------------
// C[M,N] = A[M,K] @ (Wh+Wl)[N,K]^T + bias.  CTA tile 128x128 x BK64,
// 3-stage cp.async, ONE __syncthreads per mainloop iteration.
// 8 warps, warp tile 64(M) x 32(N).  Row stride 144B: (9r+c)%8 = (r+c)%8
// distinct within each ldmatrix 8-lane transaction -> conflict-free.
// EPI: 0 fp16 out, 1 fp32 scatter via c_map, 2 GELU->fp16, 3 +resid fp32.

#define RSTRIDE 144
#define TILE_B  (128 * RSTRIDE)            // 18432
#define STAGE_B (3 * TILE_B)               // A, Bh, Bl = 55296
#define STAGES  3
#define SMEM_REQ (STAGES * STAGE_B)        // 165888

__device__ __forceinline__ void load_stage(
    uint32_t sbase, const __half* A, const __half* Bh, const __half* Bl,
    int K, int k0, int tid)
{
    int row = tid >> 1;
    int cb = (tid & 1) * 64;               // byte offset within the 128B row
    uint32_t so = (uint32_t)(row * RSTRIDE + cb);
    const char* pa = (const char*)(A  + (size_t)row * K + k0) + cb;
    const char* pb = (const char*)(Bh + (size_t)row * K + k0) + cb;
    const char* pc = (const char*)(Bl + (size_t)row * K + k0) + cb;
    #pragma unroll
    for (int q = 0; q < 4; q++) {
        CP16(sbase + so + q * 16,              pa + q * 16);
        CP16(sbase + TILE_B + so + q * 16,     pb + q * 16);
        CP16(sbase + 2 * TILE_B + so + q * 16, pc + q * 16);
    }
}

template <int EPI>
__global__ __launch_bounds__(256, 1)
void gemm_mma(const __half* __restrict__ A,
              const __half* __restrict__ Bhw, const __half* __restrict__ Blw,
              const float* __restrict__ bias,
              float* __restrict__ Cf, __half* __restrict__ Ch,
              int M, int N, int K,
              const int* __restrict__ c_map, const float* __restrict__ resid)
{
    extern __shared__ char smem[];
    uint32_t sb = smem_u32(smem);

    int tid = threadIdx.x;
    int wid = tid >> 5, lane = tid & 31;
    int warpM = wid & 1, warpN = wid >> 1;
    int bm = blockIdx.y * 128, bn = blockIdx.x * 128;
    int grp = lane >> 2, tig = lane & 3;

    const __half* pA  = A   + (size_t)bm * K;
    const __half* pBh = Bhw + (size_t)bn * K;
    const __half* pBl = Blw + (size_t)bn * K;

    int a_row = warpM * 64 + (lane & 7) + ((lane >> 3) & 1) * 8;
    uint32_t a_off = (uint32_t)(a_row * RSTRIDE + (lane >> 4) * 16);
    int b_row = warpN * 32 + (lane & 7) + (lane >> 4) * 8;
    uint32_t b_off = (uint32_t)(b_row * RSTRIDE + ((lane >> 3) & 1) * 16);

    float acc[4][4][4];
    #pragma unroll
    for (int a = 0; a < 4; a++)
        #pragma unroll
        for (int b = 0; b < 4; b++)
            #pragma unroll
            for (int c = 0; c < 4; c++) acc[a][b][c] = 0.0f;

    int nk = K / 64;

    // prologue: fill 2 stages
    load_stage(sb, pA, pBh, pBl, K, 0, tid);
    CP_COMMIT();
    load_stage(sb + STAGE_B, pA, pBh, pBl, K, 64, tid);
    CP_COMMIT();

    for (int k = 0; k < nk; k++) {
        CP_WAIT(1);
        __syncthreads();            // all warps done with compute k-1 here

        int kp = k + 2;
        if (kp < nk)
            load_stage(sb + (kp % STAGES) * STAGE_B, pA, pBh, pBl, K, kp * 64, tid);
        CP_COMMIT();

        uint32_t st = sb + (k % STAGES) * STAGE_B;
        uint32_t sA = st, sBh = st + TILE_B, sBl = st + 2 * TILE_B;

        #pragma unroll
        for (int ks = 0; ks < 4; ks++) {
            uint32_t ko = ks * 32;  // 16 fp16 = 32 bytes per k-step
            uint32_t af[4][4], bh[2][4], bl[2][4];
            #pragma unroll
            for (int mf = 0; mf < 4; mf++)
                ldsm4(af[mf], sA + a_off + (uint32_t)(mf * 16 * RSTRIDE) + ko);
            #pragma unroll
            for (int nfp = 0; nfp < 2; nfp++) {
                ldsm4(bh[nfp], sBh + b_off + (uint32_t)(nfp * 16 * RSTRIDE) + ko);
                ldsm4(bl[nfp], sBl + b_off + (uint32_t)(nfp * 16 * RSTRIDE) + ko);
            }
            #pragma unroll
            for (int mf = 0; mf < 4; mf++) {
                #pragma unroll
                for (int nf = 0; nf < 4; nf++) {
                    uint32_t b0h = bh[nf >> 1][(nf & 1) * 2];
                    uint32_t b1h = bh[nf >> 1][(nf & 1) * 2 + 1];
                    uint32_t b0l = bl[nf >> 1][(nf & 1) * 2];
                    uint32_t b1l = bl[nf >> 1][(nf & 1) * 2 + 1];
                    mma16816(acc[mf][nf], af[mf], b0h, b1h);
                    mma16816(acc[mf][nf], af[mf], b0l, b1l);
                }
            }
        }
        // no trailing barrier: next iteration's top barrier covers the hazard
    }

    // epilogue
    #pragma unroll
    for (int mf = 0; mf < 4; mf++) {
        int mbase = bm + warpM * 64 + mf * 16 + grp;
        #pragma unroll
        for (int nf = 0; nf < 4; nf++) {
            int n0 = bn + warpN * 32 + nf * 8 + 2 * tig;
            float bi0 = bias[n0], bi1 = bias[n0 + 1];
            #pragma unroll
            for (int half_ = 0; half_ < 2; half_++) {
                int m = mbase + half_ * 8;
                float v0 = acc[mf][nf][half_ * 2 + 0] + bi0;
                float v1 = acc[mf][nf][half_ * 2 + 1] + bi1;
                if (EPI == 0) {
                    __half2 hp;
                    hp.x = __float2half(v0); hp.y = __float2half(v1);
                    *(__half2*)(Ch + (size_t)m * N + n0) = hp;
                } else if (EPI == 1) {
                    size_t orow = (size_t)c_map[m];
                    Cf[orow * N + n0]     = v0;
                    Cf[orow * N + n0 + 1] = v1;
                } else if (EPI == 2) {
                    v0 = 0.5f * v0 * (1.0f + erff(v0 * 0.70710678118654752f));
                    v1 = 0.5f * v1 * (1.0f + erff(v1 * 0.70710678118654752f));
                    __half2 hp;
                    hp.x = __float2half(v0); hp.y = __float2half(v1);
                    *(__half2*)(Ch + (size_t)m * N + n0) = hp;
                } else {
                    size_t rb = (size_t)m * N + n0;
                    Cf[rb]     = v0 + resid[rb];
                    Cf[rb + 1] = v1 + resid[rb + 1];
                }
            }
        }
    }
}

// ---------------- windowed attention (fp16 in/out, parallel softmax) -------
__global__ __launch_bounds__(256)
void attn_kernel(const __half* __restrict__ qkv, const float* __restrict__ mask,
                 const float* __restrict__ rpb, __half* __restrict__ o)
{
    int w = blockIdx.x;
    int h = blockIdx.y;

    __shared__ float q[NTOK][HD];
    __shared__ float k[NTOK][HD];
    __shared__ float v[NTOK][HD];
    __shared__ float s[NTOK][52];

    int tid = threadIdx.x;
    int wid = tid >> 5, lane = tid & 31;
    const __half* base = qkv + (long)w * NTOK * (3 * CH) + h * HD;

    for (int idx = tid; idx < NTOK * (HD / 2); idx += 256) {
        int t = idx >> 4, d2 = idx & 15;
        const __half2* row = (const __half2*)(base + (long)t * (3 * CH)) + d2;
        float2 qv = __half22float2(row[0]);
        float2 kv = __half22float2(row[CH / 2]);
        float2 vv = __half22float2(row[CH]);
        q[t][d2 * 2]     = qv.x * SCALE;
        q[t][d2 * 2 + 1] = qv.y * SCALE;
        k[t][d2 * 2]     = kv.x;
        k[t][d2 * 2 + 1] = kv.y;
        v[t][d2 * 2]     = vv.x;
        v[t][d2 * 2 + 1] = vv.y;
    }
    __syncthreads();

    int wimg = w & (NWIN - 1);
    const float* mrow = mask + (long)wimg * NTOK * NTOK;
    for (int idx = tid; idx < NTOK * NTOK; idx += 256) {
        int t1 = idx / NTOK, t2 = idx % NTOK;
        float acc = 0.0f;
        #pragma unroll
        for (int d = 0; d < HD; d++) acc += q[t1][d] * k[t2][d];
        int di = (t1 / WS) - (t2 / WS) + (WS - 1);
        int dj = (t1 % WS) - (t2 % WS) + (WS - 1);
        acc += rpb[(di * (2 * WS - 1) + dj) * NHEAD + h];
        acc += mrow[idx];
        s[t1][t2] = acc;
    }
    __syncthreads();

    // warp-per-row softmax: lane covers cols lane and lane+32
    for (int row = wid; row < NTOK; row += 8) {
        float e0 = s[row][lane];
        bool has1 = (lane + 32) < NTOK;
        float e1 = has1 ? s[row][lane + 32] : -1e30f;
        float mx = fmaxf(e0, e1);
        #pragma unroll
        for (int off = 16; off; off >>= 1)
            mx = fmaxf(mx, __shfl_xor_sync(0xffffffff, mx, off));
        float x0 = __expf(e0 - mx);
        float x1 = has1 ? __expf(e1 - mx) : 0.0f;
        float sm = x0 + x1;
        #pragma unroll
        for (int off = 16; off; off >>= 1)
            sm += __shfl_xor_sync(0xffffffff, sm, off);
        float inv = 1.0f / sm;
        s[row][lane] = x0 * inv;
        if (has1) s[row][lane + 32] = x1 * inv;
    }
    __syncthreads();

    __half* ob = o + (long)w * NTOK * CH + h * HD;
    for (int idx = tid; idx < NTOK * (HD / 2); idx += 256) {
        int t = idx >> 4, d2 = idx & 15;
        int d = d2 * 2;
        float a0 = 0.0f, a1 = 0.0f;
        #pragma unroll
        for (int m = 0; m < NTOK; m++) {
            float sm = s[t][m];
            a0 += sm * v[m][d];
            a1 += sm * v[m][d + 1];
        }
        __half2 hp;
        hp.x = __float2half(a0); hp.y = __float2half(a1);
        *(__half2*)(ob + (long)t * CH + d) = hp;
    }
}

// ---------------- LayerNorm -> fp16 ----------------
__global__ __launch_bounds__(128)
void ln_kernel(const float* __restrict__ x, const float* __restrict__ g,
               const float* __restrict__ b, __half* __restrict__ o)
{
    long row = blockIdx.x;
    const float* xr = x + row * CH;
    int tid = threadIdx.x;

    float v0 = xr[tid], v1 = xr[tid + 128], v2 = xr[tid + 256];
    float sum = v0 + v1 + v2;

    __shared__ float red1[4];
    __shared__ float red2[4];
    #pragma unroll
    for (int off = 16; off; off >>= 1) sum += __shfl_xor_sync(0xffffffff, sum, off);
    if ((tid & 31) == 0) red1[tid >> 5] = sum;
    __syncthreads();
    float mu = (red1[0] + red1[1] + red1[2] + red1[3]) * (1.0f / CH);

    float d0 = v0 - mu, d1 = v1 - mu, d2 = v2 - mu;
    float sq = d0 * d0 + d1 * d1 + d2 * d2;
    #pragma unroll
    for (int off = 16; off; off >>= 1) sq += __shfl_xor_sync(0xffffffff, sq, off);
    if ((tid & 31) == 0) red2[tid >> 5] = sq;
    __syncthreads();
    float var = (red2[0] + red2[1] + red2[2] + red2[3]) * (1.0f / CH);
    float rstd = rsqrtf(var + 1e-5f);

    long base = row * CH;
    o[base + tid]       = __float2half(d0 * rstd * g[tid]       + b[tid]);
    o[base + tid + 128] = __float2half(d1 * rstd * g[tid + 128] + b[tid + 128]);
    o[base + tid + 256] = __float2half(d2 * rstd * g[tid + 256] + b[tid + 256]);
}

// ---------------- launch ----------------
extern "C" void kernel_launch(void* const* d_in, const int* in_sizes, int n_in,
                              void* d_out, int out_size)
{
    const float* x      = (const float*)d_in[0];
    const float* mask   = (const float*)d_in[1];
    const float* qkv_w  = (const float*)d_in[2];
    const float* qkv_b  = (const float*)d_in[3];
    const float* proj_w = (const float*)d_in[4];
    const float* proj_b = (const float*)d_in[5];
    const float* rpb    = (const float*)d_in[6];
    const float* n2g    = (const float*)d_in[7];
    const float* n2b    = (const float*)d_in[8];
    const float* fc1w   = (const float*)d_in[9];
    const float* fc1b   = (const float*)d_in[10];
    const float* fc2w   = (const float*)d_in[11];
    const float* fc2b   = (const float*)d_in[12];
    float* out = (float*)d_out;

    void *p;
    #define GSYM(sym, var, ty) cudaGetSymbolAddress(&p, sym); ty* var = (ty*)p;
    GSYM(g_xg, xg, __half)
    GSYM(g_qkv, qkv, __half)
    GSYM(g_at, at, __half)
    GSYM(g_x2, x2, float)
    GSYM(g_hn, hn, __half)
    GSYM(g_hid, hid, __half)
    GSYM(g_map, map, int)
    GSYM(g_wqkv_hi, wqkv_hi, __half) GSYM(g_wqkv_lo, wqkv_lo, __half)
    GSYM(g_wprj_hi, wprj_hi, __half) GSYM(g_wprj_lo, wprj_lo, __half)
    GSYM(g_wf1_hi, wf1_hi, __half) GSYM(g_wf1_lo, wf1_lo, __half)
    GSYM(g_wf2_hi, wf2_hi, __half) GSYM(g_wf2_lo, wf2_lo, __half)
    #undef GSYM

    cudaFuncSetAttribute(gemm_mma<0>, cudaFuncAttributeMaxDynamicSharedMemorySize, SMEM_REQ);
    cudaFuncSetAttribute(gemm_mma<1>, cudaFuncAttributeMaxDynamicSharedMemorySize, SMEM_REQ);
    cudaFuncSetAttribute(gemm_mma<2>, cudaFuncAttributeMaxDynamicSharedMemorySize, SMEM_REQ);
    cudaFuncSetAttribute(gemm_mma<3>, cudaFuncAttributeMaxDynamicSharedMemorySize, SMEM_REQ);

    build_maps_kernel<<<(MROWS + 255) / 256, 256>>>(map);

    long nx = (long)MROWS * CH;
    conv_gather<<<(int)((nx + 255) / 256), 256>>>(x, map, xg);
    conv_wsplit<<<(3 * CH * CH + 255) / 256, 256>>>(qkv_w, wqkv_hi, wqkv_lo, 3 * CH * CH);
    conv_wsplit<<<(CH * CH + 255) / 256, 256>>>(proj_w, wprj_hi, wprj_lo, CH * CH);
    conv_wsplit<<<(HID * CH + 255) / 256, 256>>>(fc1w, wf1_hi, wf1_lo, HID * CH);
    conv_wsplit<<<(CH * HID + 255) / 256, 256>>>(fc2w, wf2_hi, wf2_lo, CH * HID);

    // QKV -> fp16 qkv (windowed order)
    gemm_mma<0><<<dim3((3 * CH) / 128, MROWS / 128), 256, SMEM_REQ>>>(
        xg, wqkv_hi, wqkv_lo, qkv_b, nullptr, qkv,
        MROWS, 3 * CH, CH, nullptr, nullptr);

    attn_kernel<<<dim3(BATCH * NWIN, NHEAD), 256>>>(qkv, mask, rpb, at);

    // proj + scatter to image order -> x2 (fp32)
    gemm_mma<1><<<dim3(CH / 128, MROWS / 128), 256, SMEM_REQ>>>(
        at, wprj_hi, wprj_lo, proj_b, x2, nullptr,
        MROWS, CH, CH, map, nullptr);

    ln_kernel<<<MROWS, 128>>>(x2, n2g, n2b, hn);

    // FC1 + GELU -> fp16
    gemm_mma<2><<<dim3(HID / 128, MROWS / 128), 256, SMEM_REQ>>>(
        hn, wf1_hi, wf1_lo, fc1b, nullptr, hid,
        MROWS, HID, CH, nullptr, nullptr);

    // FC2 + residual -> out (fp32)
    gemm_mma<3><<<dim3(CH / 128, MROWS / 128), 256, SMEM_REQ>>>(
        hid, wf2_hi, wf2_lo, fc2b, out, nullptr,
        MROWS, CH, HID, nullptr, x2);
}

// round 12
// speedup vs baseline: 1.0316x; 1.0316x over previous
#include <cuda_runtime.h>
#include <cuda_fp16.h>
#include <math.h>
#include <stdint.h>

// ---------------- problem constants ----------------
#define BATCH 16
#define HW    56
#define CH    384
#define NHEAD 12
#define WS    7
#define NTOK  49
#define HD    32
#define NWIN  64
#define MROWS 50176
#define HID   1536
#define SCALE 0.17677669529663687f

// ---------------- scratch ----------------
__device__ __half g_xg[(long)MROWS * CH];
__device__ __half g_qkv[(long)MROWS * 3 * CH];
__device__ __half g_at[(long)MROWS * CH];
__device__ float  g_x2[(long)MROWS * CH];
__device__ __half g_hn[(long)MROWS * CH];
__device__ __half g_hid[(long)MROWS * HID];
__device__ int    g_map[MROWS];
__device__ __half g_wqkv_hi[3 * CH * CH], g_wqkv_lo[3 * CH * CH];
__device__ __half g_wprj_hi[CH * CH],     g_wprj_lo[CH * CH];
__device__ __half g_wf1_hi[HID * CH],     g_wf1_lo[HID * CH];
__device__ __half g_wf2_hi[CH * HID],     g_wf2_lo[CH * HID];

// ---------------- helpers ----------------
__device__ __forceinline__ uint32_t smem_u32(const void* p) {
    uint32_t a;
    asm("{ .reg .u64 t; cvta.to.shared.u64 t, %1; cvt.u32.u64 %0, t; }" : "=r"(a) : "l"(p));
    return a;
}

#define CP16(dst, src) asm volatile("cp.async.cg.shared.global [%0], [%1], 16;\n" :: "r"(dst), "l"(src))
#define CP_COMMIT()    asm volatile("cp.async.commit_group;\n" ::: "memory")
#define CP_WAIT(n)     asm volatile("cp.async.wait_group %0;\n" :: "n"(n) : "memory")

__device__ __forceinline__ void ldsm4(uint32_t* r, uint32_t addr) {
    asm volatile("ldmatrix.sync.aligned.m8n8.x4.shared.b16 {%0,%1,%2,%3}, [%4];"
                 : "=r"(r[0]), "=r"(r[1]), "=r"(r[2]), "=r"(r[3]) : "r"(addr));
}

__device__ __forceinline__ void mma16816(float* c, const uint32_t* a, uint32_t b0, uint32_t b1) {
    asm volatile(
        "mma.sync.aligned.m16n8k16.row.col.f32.f16.f16.f32 "
        "{%0,%1,%2,%3}, {%4,%5,%6,%7}, {%8,%9}, {%0,%1,%2,%3};\n"
        : "+f"(c[0]), "+f"(c[1]), "+f"(c[2]), "+f"(c[3])
        : "r"(a[0]), "r"(a[1]), "r"(a[2]), "r"(a[3]), "r"(b0), "r"(b1));
}

// ---------------- row permutation map ----------------
__global__ void build_maps_kernel(int* __restrict__ map) {
    int r = blockIdx.x * 256 + threadIdx.x;
    if (r >= MROWS) return;
    int w = r / NTOK, t = r % NTOK;
    int b = w / NWIN, wrem = w % NWIN;
    int wi = wrem / 8, wj = wrem % 8;
    int ti = t / WS, tj = t % WS;
    int h0 = (wi * WS + ti + 3) % HW;
    int w0 = (wj * WS + tj + 3) % HW;
    map[r] = b * (HW * HW) + h0 * HW + w0;
}

// ---------------- conversions ----------------
__device__ __forceinline__ void split_fp16(float v, __half& h, __half& l) {
    h = __float2half(v);
    l = __float2half(v - __half2float(h));
}

__global__ void conv_wsplit(const float* __restrict__ src,
                            __half* __restrict__ hi, __half* __restrict__ lo, long n) {
    long i = (long)blockIdx.x * 256 + threadIdx.x;
    if (i >= n) return;
    __half h, l;
    split_fp16(src[i], h, l);
    hi[i] = h; lo[i] = l;
}

__global__ void conv_gather(const float* __restrict__ x, const int* __restrict__ map,
                            __half* __restrict__ o) {
    long i = (long)blockIdx.x * 256 + threadIdx.x;
    if (i >= (long)MROWS * CH) return;
    long r = i / CH, c = i % CH;
    o[i] = __float2half(x[(long)map[r] * CH + c]);
}

// ---------------- pipelined fp16x2 HMMA GEMM ------------------------------
// C[M,N] = A[M,K] @ (Wh+Wl)[N,K]^T + bias.  CTA tile 128x128xBK32,
// 4-stage cp.async, single barrier per mainloop iteration.
// 8 warps, warp tile 64(M) x 32(N).
// EPI: 0 fp16 out, 1 fp32 scatter via c_map, 2 GELU->fp16, 3 +resid fp32.

#define RSTRIDE 80
#define TILE_B  (128 * RSTRIDE)            // 10240
#define STAGE_B (3 * TILE_B)               // A, Bh, Bl = 30720
#define STAGES  4
#define SMEM_REQ (STAGES * STAGE_B)        // 122880

__device__ __forceinline__ void load_stage(
    uint32_t sbase, const __half* A, const __half* Bh, const __half* Bl,
    int K, int k0, int tid)
{
    int row = tid >> 1;
    int c0 = (tid & 1) * 2;
    uint32_t so = (uint32_t)(row * RSTRIDE + c0 * 16);
    size_t go = (size_t)row * K + k0 + c0 * 8;
    const char* pa = (const char*)(A + go);
    const char* pb = (const char*)(Bh + go);
    const char* pc = (const char*)(Bl + go);
    CP16(sbase + so,                    pa);
    CP16(sbase + so + 16,               pa + 16);
    CP16(sbase + TILE_B + so,           pb);
    CP16(sbase + TILE_B + so + 16,      pb + 16);
    CP16(sbase + 2 * TILE_B + so,       pc);
    CP16(sbase + 2 * TILE_B + so + 16,  pc + 16);
}

template <int EPI>
__global__ __launch_bounds__(256, 1)
void gemm_mma(const __half* __restrict__ A,
              const __half* __restrict__ Bhw, const __half* __restrict__ Blw,
              const float* __restrict__ bias,
              float* __restrict__ Cf, __half* __restrict__ Ch,
              int M, int N, int K,
              const int* __restrict__ c_map, const float* __restrict__ resid)
{
    extern __shared__ char smem[];
    uint32_t sb = smem_u32(smem);

    int tid = threadIdx.x;
    int wid = tid >> 5, lane = tid & 31;
    int warpM = wid & 1, warpN = wid >> 1;
    int bm = blockIdx.y * 128, bn = blockIdx.x * 128;
    int grp = lane >> 2, tig = lane & 3;

    const __half* pA  = A   + (size_t)bm * K;
    const __half* pBh = Bhw + (size_t)bn * K;
    const __half* pBl = Blw + (size_t)bn * K;

    int a_row = warpM * 64 + (lane & 7) + ((lane >> 3) & 1) * 8;
    uint32_t a_off = (uint32_t)(a_row * RSTRIDE + (lane >> 4) * 16);
    int b_row = warpN * 32 + (lane & 7) + (lane >> 4) * 8;
    uint32_t b_off = (uint32_t)(b_row * RSTRIDE + ((lane >> 3) & 1) * 16);

    float acc[4][4][4];
    #pragma unroll
    for (int a = 0; a < 4; a++)
        #pragma unroll
        for (int b = 0; b < 4; b++)
            #pragma unroll
            for (int c = 0; c < 4; c++) acc[a][b][c] = 0.0f;

    int nk = K / 32;

    #pragma unroll
    for (int s = 0; s < STAGES - 1; s++) {
        if (s < nk) load_stage(sb + s * STAGE_B, pA, pBh, pBl, K, s * 32, tid);
        CP_COMMIT();
    }

    for (int k = 0; k < nk; k++) {
        CP_WAIT(STAGES - 2);
        __syncthreads();   // orders all warps' compute k-1 before prefetch below

        int kp = k + STAGES - 1;
        if (kp < nk)
            load_stage(sb + (kp % STAGES) * STAGE_B, pA, pBh, pBl, K, kp * 32, tid);
        CP_COMMIT();

        uint32_t st = sb + (k % STAGES) * STAGE_B;
        uint32_t sA = st, sBh = st + TILE_B, sBl = st + 2 * TILE_B;

        #pragma unroll
        for (int ks = 0; ks < 2; ks++) {
            uint32_t ko = ks * 32;
            uint32_t af[4][4], bh[2][4], bl[2][4];
            #pragma unroll
            for (int mf = 0; mf < 4; mf++)
                ldsm4(af[mf], sA + a_off + (uint32_t)(mf * 16 * RSTRIDE) + ko);
            #pragma unroll
            for (int nfp = 0; nfp < 2; nfp++) {
                ldsm4(bh[nfp], sBh + b_off + (uint32_t)(nfp * 16 * RSTRIDE) + ko);
                ldsm4(bl[nfp], sBl + b_off + (uint32_t)(nfp * 16 * RSTRIDE) + ko);
            }
            #pragma unroll
            for (int mf = 0; mf < 4; mf++) {
                #pragma unroll
                for (int nf = 0; nf < 4; nf++) {
                    uint32_t b0h = bh[nf >> 1][(nf & 1) * 2];
                    uint32_t b1h = bh[nf >> 1][(nf & 1) * 2 + 1];
                    uint32_t b0l = bl[nf >> 1][(nf & 1) * 2];
                    uint32_t b1l = bl[nf >> 1][(nf & 1) * 2 + 1];
                    mma16816(acc[mf][nf], af[mf], b0h, b1h);
                    mma16816(acc[mf][nf], af[mf], b0l, b1l);
                }
            }
        }
        // no trailing barrier: next iteration's top barrier covers reuse hazard
    }

    // epilogue
    #pragma unroll
    for (int mf = 0; mf < 4; mf++) {
        int mbase = bm + warpM * 64 + mf * 16 + grp;
        #pragma unroll
        for (int nf = 0; nf < 4; nf++) {
            int n0 = bn + warpN * 32 + nf * 8 + 2 * tig;
            float bi0 = bias[n0], bi1 = bias[n0 + 1];
            #pragma unroll
            for (int half_ = 0; half_ < 2; half_++) {
                int m = mbase + half_ * 8;
                float v0 = acc[mf][nf][half_ * 2 + 0] + bi0;
                float v1 = acc[mf][nf][half_ * 2 + 1] + bi1;
                if (EPI == 0) {
                    __half2 hp;
                    hp.x = __float2half(v0); hp.y = __float2half(v1);
                    *(__half2*)(Ch + (size_t)m * N + n0) = hp;
                } else if (EPI == 1) {
                    size_t orow = (size_t)c_map[m];
                    Cf[orow * N + n0]     = v0;
                    Cf[orow * N + n0 + 1] = v1;
                } else if (EPI == 2) {
                    v0 = 0.5f * v0 * (1.0f + erff(v0 * 0.70710678118654752f));
                    v1 = 0.5f * v1 * (1.0f + erff(v1 * 0.70710678118654752f));
                    __half2 hp;
                    hp.x = __float2half(v0); hp.y = __float2half(v1);
                    *(__half2*)(Ch + (size_t)m * N + n0) = hp;
                } else {
                    size_t rb = (size_t)m * N + n0;
                    Cf[rb]     = v0 + resid[rb];
                    Cf[rb + 1] = v1 + resid[rb + 1];
                }
            }
        }
    }
}

// ---------------- windowed attention (fp16 in/out, parallel softmax) -------
__global__ __launch_bounds__(256)
void attn_kernel(const __half* __restrict__ qkv, const float* __restrict__ mask,
                 const float* __restrict__ rpb, __half* __restrict__ o)
{
    int w = blockIdx.x;
    int h = blockIdx.y;

    __shared__ float q[NTOK][HD];
    __shared__ float k[NTOK][HD];
    __shared__ float v[NTOK][HD];
    __shared__ float s[NTOK][52];

    int tid = threadIdx.x;
    int wid = tid >> 5, lane = tid & 31;
    const __half* base = qkv + (long)w * NTOK * (3 * CH) + h * HD;

    for (int idx = tid; idx < NTOK * (HD / 2); idx += 256) {
        int t = idx >> 4, d2 = idx & 15;
        const __half2* row = (const __half2*)(base + (long)t * (3 * CH)) + d2;
        float2 qv = __half22float2(row[0]);
        float2 kv = __half22float2(row[CH / 2]);
        float2 vv = __half22float2(row[CH]);
        q[t][d2 * 2]     = qv.x * SCALE;
        q[t][d2 * 2 + 1] = qv.y * SCALE;
        k[t][d2 * 2]     = kv.x;
        k[t][d2 * 2 + 1] = kv.y;
        v[t][d2 * 2]     = vv.x;
        v[t][d2 * 2 + 1] = vv.y;
    }
    __syncthreads();

    int wimg = w & (NWIN - 1);
    const float* mrow = mask + (long)wimg * NTOK * NTOK;
    for (int idx = tid; idx < NTOK * NTOK; idx += 256) {
        int t1 = idx / NTOK, t2 = idx % NTOK;
        float acc = 0.0f;
        #pragma unroll
        for (int d = 0; d < HD; d++) acc += q[t1][d] * k[t2][d];
        int di = (t1 / WS) - (t2 / WS) + (WS - 1);
        int dj = (t1 % WS) - (t2 % WS) + (WS - 1);
        acc += rpb[(di * (2 * WS - 1) + dj) * NHEAD + h];
        acc += mrow[idx];
        s[t1][t2] = acc;
    }
    __syncthreads();

    // warp-per-row softmax: lane covers cols lane and lane+32
    for (int row = wid; row < NTOK; row += 8) {
        float e0 = s[row][lane];
        bool has1 = (lane + 32) < NTOK;
        float e1 = has1 ? s[row][lane + 32] : -1e30f;
        float mx = fmaxf(e0, e1);
        #pragma unroll
        for (int off = 16; off; off >>= 1)
            mx = fmaxf(mx, __shfl_xor_sync(0xffffffff, mx, off));
        float x0 = __expf(e0 - mx);
        float x1 = has1 ? __expf(e1 - mx) : 0.0f;
        float sm = x0 + x1;
        #pragma unroll
        for (int off = 16; off; off >>= 1)
            sm += __shfl_xor_sync(0xffffffff, sm, off);
        float inv = 1.0f / sm;
        s[row][lane] = x0 * inv;
        if (has1) s[row][lane + 32] = x1 * inv;
    }
    __syncthreads();

    __half* ob = o + (long)w * NTOK * CH + h * HD;
    for (int idx = tid; idx < NTOK * (HD / 2); idx += 256) {
        int t = idx >> 4, d2 = idx & 15;
        int d = d2 * 2;
        float a0 = 0.0f, a1 = 0.0f;
        #pragma unroll
        for (int m = 0; m < NTOK; m++) {
            float sm = s[t][m];
            a0 += sm * v[m][d];
            a1 += sm * v[m][d + 1];
        }
        __half2 hp;
        hp.x = __float2half(a0); hp.y = __float2half(a1);
        *(__half2*)(ob + (long)t * CH + d) = hp;
    }
}

// ---------------- LayerNorm -> fp16 ----------------
__global__ __launch_bounds__(128)
void ln_kernel(const float* __restrict__ x, const float* __restrict__ g,
               const float* __restrict__ b, __half* __restrict__ o)
{
    long row = blockIdx.x;
    const float* xr = x + row * CH;
    int tid = threadIdx.x;

    float v0 = xr[tid], v1 = xr[tid + 128], v2 = xr[tid + 256];
    float sum = v0 + v1 + v2;

    __shared__ float red1[4];
    __shared__ float red2[4];
    #pragma unroll
    for (int off = 16; off; off >>= 1) sum += __shfl_xor_sync(0xffffffff, sum, off);
    if ((tid & 31) == 0) red1[tid >> 5] = sum;
    __syncthreads();
    float mu = (red1[0] + red1[1] + red1[2] + red1[3]) * (1.0f / CH);

    float d0 = v0 - mu, d1 = v1 - mu, d2 = v2 - mu;
    float sq = d0 * d0 + d1 * d1 + d2 * d2;
    #pragma unroll
    for (int off = 16; off; off >>= 1) sq += __shfl_xor_sync(0xffffffff, sq, off);
    if ((tid & 31) == 0) red2[tid >> 5] = sq;
    __syncthreads();
    float var = (red2[0] + red2[1] + red2[2] + red2[3]) * (1.0f / CH);
    float rstd = rsqrtf(var + 1e-5f);

    long base = row * CH;
    o[base + tid]       = __float2half(d0 * rstd * g[tid]       + b[tid]);
    o[base + tid + 128] = __float2half(d1 * rstd * g[tid + 128] + b[tid + 128]);
    o[base + tid + 256] = __float2half(d2 * rstd * g[tid + 256] + b[tid + 256]);
}

// ---------------- launch ----------------
extern "C" void kernel_launch(void* const* d_in, const int* in_sizes, int n_in,
                              void* d_out, int out_size)
{
    const float* x      = (const float*)d_in[0];
    const float* mask   = (const float*)d_in[1];
    const float* qkv_w  = (const float*)d_in[2];
    const float* qkv_b  = (const float*)d_in[3];
    const float* proj_w = (const float*)d_in[4];
    const float* proj_b = (const float*)d_in[5];
    const float* rpb    = (const float*)d_in[6];
    const float* n2g    = (const float*)d_in[7];
    const float* n2b    = (const float*)d_in[8];
    const float* fc1w   = (const float*)d_in[9];
    const float* fc1b   = (const float*)d_in[10];
    const float* fc2w   = (const float*)d_in[11];
    const float* fc2b   = (const float*)d_in[12];
    float* out = (float*)d_out;

    void *p;
    #define GSYM(sym, var, ty) cudaGetSymbolAddress(&p, sym); ty* var = (ty*)p;
    GSYM(g_xg, xg, __half)
    GSYM(g_qkv, qkv, __half)
    GSYM(g_at, at, __half)
    GSYM(g_x2, x2, float)
    GSYM(g_hn, hn, __half)
    GSYM(g_hid, hid, __half)
    GSYM(g_map, map, int)
    GSYM(g_wqkv_hi, wqkv_hi, __half) GSYM(g_wqkv_lo, wqkv_lo, __half)
    GSYM(g_wprj_hi, wprj_hi, __half) GSYM(g_wprj_lo, wprj_lo, __half)
    GSYM(g_wf1_hi, wf1_hi, __half) GSYM(g_wf1_lo, wf1_lo, __half)
    GSYM(g_wf2_hi, wf2_hi, __half) GSYM(g_wf2_lo, wf2_lo, __half)
    #undef GSYM

    cudaFuncSetAttribute(gemm_mma<0>, cudaFuncAttributeMaxDynamicSharedMemorySize, SMEM_REQ);
    cudaFuncSetAttribute(gemm_mma<1>, cudaFuncAttributeMaxDynamicSharedMemorySize, SMEM_REQ);
    cudaFuncSetAttribute(gemm_mma<2>, cudaFuncAttributeMaxDynamicSharedMemorySize, SMEM_REQ);
    cudaFuncSetAttribute(gemm_mma<3>, cudaFuncAttributeMaxDynamicSharedMemorySize, SMEM_REQ);

    build_maps_kernel<<<(MROWS + 255) / 256, 256>>>(map);

    long nx = (long)MROWS * CH;
    conv_gather<<<(int)((nx + 255) / 256), 256>>>(x, map, xg);
    conv_wsplit<<<(3 * CH * CH + 255) / 256, 256>>>(qkv_w, wqkv_hi, wqkv_lo, 3 * CH * CH);
    conv_wsplit<<<(CH * CH + 255) / 256, 256>>>(proj_w, wprj_hi, wprj_lo, CH * CH);
    conv_wsplit<<<(HID * CH + 255) / 256, 256>>>(fc1w, wf1_hi, wf1_lo, HID * CH);
    conv_wsplit<<<(CH * HID + 255) / 256, 256>>>(fc2w, wf2_hi, wf2_lo, CH * HID);

    // QKV -> fp16 qkv (windowed order)
    gemm_mma<0><<<dim3((3 * CH) / 128, MROWS / 128), 256, SMEM_REQ>>>(
        xg, wqkv_hi, wqkv_lo, qkv_b, nullptr, qkv,
        MROWS, 3 * CH, CH, nullptr, nullptr);

    attn_kernel<<<dim3(BATCH * NWIN, NHEAD), 256>>>(qkv, mask, rpb, at);

    // proj + scatter to image order -> x2 (fp32)
    gemm_mma<1><<<dim3(CH / 128, MROWS / 128), 256, SMEM_REQ>>>(
        at, wprj_hi, wprj_lo, proj_b, x2, nullptr,
        MROWS, CH, CH, map, nullptr);

    ln_kernel<<<MROWS, 128>>>(x2, n2g, n2b, hn);

    // FC1 + GELU -> fp16
    gemm_mma<2><<<dim3(HID / 128, MROWS / 128), 256, SMEM_REQ>>>(
        hn, wf1_hi, wf1_lo, fc1b, nullptr, hid,
        MROWS, HID, CH, nullptr, nullptr);

    // FC2 + residual -> out (fp32)
    gemm_mma<3><<<dim3(CH / 128, MROWS / 128), 256, SMEM_REQ>>>(
        hid, wf2_hi, wf2_lo, fc2b, out, nullptr,
        MROWS, CH, HID, nullptr, x2);
}

// round 14
// speedup vs baseline: 1.0351x; 1.0034x over previous
#include <cuda_runtime.h>
#include <cuda_fp16.h>
#include <math.h>
#include <stdint.h>

// ---------------- problem constants ----------------
#define BATCH 16
#define HW    56
#define CH    384
#define NHEAD 12
#define WS    7
#define NTOK  49
#define HD    32
#define NWIN  64
#define MROWS 50176
#define HID   1536
#define SCALE 0.17677669529663687f

// ---------------- scratch ----------------
__device__ __half g_xg[(long)MROWS * CH];
__device__ __half g_qkv[(long)MROWS * 3 * CH];
__device__ __half g_at[(long)MROWS * CH];
__device__ float  g_x2[(long)MROWS * CH];
__device__ __half g_hn[(long)MROWS * CH];
__device__ __half g_hid[(long)MROWS * HID];
__device__ int    g_map[MROWS];
__device__ __half g_wqkv_hi[3 * CH * CH], g_wqkv_lo[3 * CH * CH];
__device__ __half g_wprj_hi[CH * CH],     g_wprj_lo[CH * CH];
__device__ __half g_wf1_hi[HID * CH],     g_wf1_lo[HID * CH];
__device__ __half g_wf2_hi[CH * HID],     g_wf2_lo[CH * HID];

// ---------------- helpers ----------------
__device__ __forceinline__ uint32_t smem_u32(const void* p) {
    uint32_t a;
    asm("{ .reg .u64 t; cvta.to.shared.u64 t, %1; cvt.u32.u64 %0, t; }" : "=r"(a) : "l"(p));
    return a;
}

#define CP16(dst, src) asm volatile("cp.async.cg.shared.global [%0], [%1], 16;\n" :: "r"(dst), "l"(src))
#define CP_COMMIT()    asm volatile("cp.async.commit_group;\n" ::: "memory")
#define CP_WAIT(n)     asm volatile("cp.async.wait_group %0;\n" :: "n"(n) : "memory")

__device__ __forceinline__ void ldsm4(uint32_t* r, uint32_t addr) {
    asm volatile("ldmatrix.sync.aligned.m8n8.x4.shared.b16 {%0,%1,%2,%3}, [%4];"
                 : "=r"(r[0]), "=r"(r[1]), "=r"(r[2]), "=r"(r[3]) : "r"(addr));
}

__device__ __forceinline__ void mma16816(float* c, const uint32_t* a, uint32_t b0, uint32_t b1) {
    asm volatile(
        "mma.sync.aligned.m16n8k16.row.col.f32.f16.f16.f32 "
        "{%0,%1,%2,%3}, {%4,%5,%6,%7}, {%8,%9}, {%0,%1,%2,%3};\n"
        : "+f"(c[0]), "+f"(c[1]), "+f"(c[2]), "+f"(c[3])
        : "r"(a[0]), "r"(a[1]), "r"(a[2]), "r"(a[3]), "r"(b0), "r"(b1));
}

// ---------------- row permutation map ----------------
__global__ void build_maps_kernel(int* __restrict__ map) {
    int r = blockIdx.x * 256 + threadIdx.x;
    if (r >= MROWS) return;
    int w = r / NTOK, t = r % NTOK;
    int b = w / NWIN, wrem = w % NWIN;
    int wi = wrem / 8, wj = wrem % 8;
    int ti = t / WS, tj = t % WS;
    int h0 = (wi * WS + ti + 3) % HW;
    int w0 = (wj * WS + tj + 3) % HW;
    map[r] = b * (HW * HW) + h0 * HW + w0;
}

// ---------------- conversions ----------------
__device__ __forceinline__ void split_fp16(float v, __half& h, __half& l) {
    h = __float2half(v);
    l = __float2half(v - __half2float(h));
}

// all four weight splits in ONE launch
#define S_QKV (3 * CH * CH)      // 442368
#define S_PRJ (CH * CH)          // 147456
#define S_FC1 (HID * CH)         // 589824
#define S_FC2 (CH * HID)         // 589824
#define S_ALL (S_QKV + S_PRJ + S_FC1 + S_FC2)

__global__ void conv_wsplit_all(
    const float* __restrict__ w0, __half* __restrict__ h0, __half* __restrict__ l0,
    const float* __restrict__ w1, __half* __restrict__ h1, __half* __restrict__ l1,
    const float* __restrict__ w2, __half* __restrict__ h2, __half* __restrict__ l2,
    const float* __restrict__ w3, __half* __restrict__ h3, __half* __restrict__ l3)
{
    long i = (long)blockIdx.x * 256 + threadIdx.x;
    if (i >= S_ALL) return;
    const float* src; __half *hi, *lo; long j = i;
    if (j < S_QKV)                 { src = w0; hi = h0; lo = l0; }
    else if ((j -= S_QKV) < S_PRJ) { src = w1; hi = h1; lo = l1; }
    else if ((j -= S_PRJ) < S_FC1) { src = w2; hi = h2; lo = l2; }
    else { j -= S_FC1;               src = w3; hi = h3; lo = l3; }
    __half h, l;
    split_fp16(src[j], h, l);
    hi[j] = h; lo[j] = l;
}

__global__ void conv_gather(const float* __restrict__ x, const int* __restrict__ map,
                            __half* __restrict__ o) {
    long i = (long)blockIdx.x * 256 + threadIdx.x;
    if (i >= (long)MROWS * CH) return;
    long r = i / CH, c = i % CH;
    o[i] = __float2half(x[(long)map[r] * CH + c]);
}

// ---------------- pipelined fp16x2 HMMA GEMM ------------------------------
// C[M,N] = A[M,K] @ (Wh+Wl)[N,K]^T + bias.  CTA tile 256x128 x BK32,
// 4-stage cp.async.  8 warps: warpM = wid&3 (64 rows), warpN = wid>>2 (64 cols).
// Per k16 per warp: 4 A-LDSM + 8 B-LDSM -> 64 HMMA (2x better ratio than 64x32).
// EPI: 0 fp16 out, 1 fp32 scatter via c_map, 2 GELU->fp16, 3 +resid fp32.

#define RSTRIDE 80
#define ATILE_B (256 * RSTRIDE)            // 20480
#define BTILE_B (128 * RSTRIDE)            // 10240
#define STAGE_B (ATILE_B + 2 * BTILE_B)    // 40960
#define STAGES  4
#define SMEM_REQ (STAGES * STAGE_B)        // 163840

__device__ __forceinline__ void load_stage(
    uint32_t sbase, const __half* A, const __half* Bh, const __half* Bl,
    int K, int k0, int tid)
{
    // A: 256 rows x 64B, one row per thread
    {
        uint32_t so = sbase + (uint32_t)(tid * RSTRIDE);
        const char* pa = (const char*)(A + (size_t)tid * K + k0);
        CP16(so,      pa);
        CP16(so + 16, pa + 16);
        CP16(so + 32, pa + 32);
        CP16(so + 48, pa + 48);
    }
    // B: 128 rows hi (threads 0-127) + 128 rows lo (threads 128-255)
    {
        int r = tid & 127;
        const __half* src = (tid < 128) ? Bh : Bl;
        uint32_t so = sbase + ATILE_B + (tid < 128 ? 0u : (uint32_t)BTILE_B)
                    + (uint32_t)(r * RSTRIDE);
        const char* pb = (const char*)(src + (size_t)r * K + k0);
        CP16(so,      pb);
        CP16(so + 16, pb + 16);
        CP16(so + 32, pb + 32);
        CP16(so + 48, pb + 48);
    }
}

template <int EPI>
__global__ __launch_bounds__(256, 1)
void gemm_mma(const __half* __restrict__ A,
              const __half* __restrict__ Bhw, const __half* __restrict__ Blw,
              const float* __restrict__ bias,
              float* __restrict__ Cf, __half* __restrict__ Ch,
              int M, int N, int K,
              const int* __restrict__ c_map, const float* __restrict__ resid)
{
    extern __shared__ char smem[];
    uint32_t sb = smem_u32(smem);

    int tid = threadIdx.x;
    int wid = tid >> 5, lane = tid & 31;
    int warpM = wid & 3, warpN = wid >> 2;
    int bm = blockIdx.y * 256, bn = blockIdx.x * 128;
    int grp = lane >> 2, tig = lane & 3;

    const __half* pA  = A   + (size_t)bm * K;
    const __half* pBh = Bhw + (size_t)bn * K;
    const __half* pBl = Blw + (size_t)bn * K;

    int a_row = warpM * 64 + (lane & 7) + ((lane >> 3) & 1) * 8;
    uint32_t a_off = (uint32_t)(a_row * RSTRIDE + (lane >> 4) * 16);
    int b_row = warpN * 64 + (lane & 7) + (lane >> 4) * 8;
    uint32_t b_off = (uint32_t)(b_row * RSTRIDE + ((lane >> 3) & 1) * 16);

    float acc[4][8][4];
    #pragma unroll
    for (int a = 0; a < 4; a++)
        #pragma unroll
        for (int b = 0; b < 8; b++)
            #pragma unroll
            for (int c = 0; c < 4; c++) acc[a][b][c] = 0.0f;

    int nk = K / 32;

    #pragma unroll
    for (int s = 0; s < STAGES - 1; s++) {
        if (s < nk) load_stage(sb + s * STAGE_B, pA, pBh, pBl, K, s * 32, tid);
        CP_COMMIT();
    }

    for (int k = 0; k < nk; k++) {
        CP_WAIT(STAGES - 2);
        __syncthreads();

        int kp = k + STAGES - 1;
        if (kp < nk)
            load_stage(sb + (kp % STAGES) * STAGE_B, pA, pBh, pBl, K, kp * 32, tid);
        CP_COMMIT();

        uint32_t st = sb + (k % STAGES) * STAGE_B;
        uint32_t sA = st, sBh = st + ATILE_B, sBl = st + ATILE_B + BTILE_B;

        #pragma unroll
        for (int ks = 0; ks < 2; ks++) {
            uint32_t ko = ks * 32;
            uint32_t af[4][4];
            #pragma unroll
            for (int mf = 0; mf < 4; mf++)
                ldsm4(af[mf], sA + a_off + (uint32_t)(mf * 16 * RSTRIDE) + ko);
            #pragma unroll
            for (int nfp = 0; nfp < 4; nfp++) {
                uint32_t bh[4], bl[4];
                ldsm4(bh, sBh + b_off + (uint32_t)(nfp * 16 * RSTRIDE) + ko);
                ldsm4(bl, sBl + b_off + (uint32_t)(nfp * 16 * RSTRIDE) + ko);
                #pragma unroll
                for (int mf = 0; mf < 4; mf++) {
                    mma16816(acc[mf][2 * nfp],     af[mf], bh[0], bh[1]);
                    mma16816(acc[mf][2 * nfp],     af[mf], bl[0], bl[1]);
                    mma16816(acc[mf][2 * nfp + 1], af[mf], bh[2], bh[3]);
                    mma16816(acc[mf][2 * nfp + 1], af[mf], bl[2], bl[3]);
                }
            }
        }
        __syncthreads();
    }

    // epilogue: warp covers rows [warpM*64, +64), cols [warpN*64, +64)
    #pragma unroll
    for (int mf = 0; mf < 4; mf++) {
        int mbase = bm + warpM * 64 + mf * 16 + grp;
        #pragma unroll
        for (int nf = 0; nf < 8; nf++) {
            int n0 = bn + warpN * 64 + nf * 8 + 2 * tig;
            float bi0 = bias[n0], bi1 = bias[n0 + 1];
            #pragma unroll
            for (int half_ = 0; half_ < 2; half_++) {
                int m = mbase + half_ * 8;
                float v0 = acc[mf][nf][half_ * 2 + 0] + bi0;
                float v1 = acc[mf][nf][half_ * 2 + 1] + bi1;
                if (EPI == 0) {
                    __half2 hp;
                    hp.x = __float2half(v0); hp.y = __float2half(v1);
                    *(__half2*)(Ch + (size_t)m * N + n0) = hp;
                } else if (EPI == 1) {
                    size_t orow = (size_t)c_map[m];
                    Cf[orow * N + n0]     = v0;
                    Cf[orow * N + n0 + 1] = v1;
                } else if (EPI == 2) {
                    v0 = 0.5f * v0 * (1.0f + erff(v0 * 0.70710678118654752f));
                    v1 = 0.5f * v1 * (1.0f + erff(v1 * 0.70710678118654752f));
                    __half2 hp;
                    hp.x = __float2half(v0); hp.y = __float2half(v1);
                    *(__half2*)(Ch + (size_t)m * N + n0) = hp;
                } else {
                    size_t rb = (size_t)m * N + n0;
                    Cf[rb]     = v0 + resid[rb];
                    Cf[rb + 1] = v1 + resid[rb + 1];
                }
            }
        }
    }
}

// ---------------- windowed attention (fp16 in/out, parallel softmax) -------
__global__ __launch_bounds__(256)
void attn_kernel(const __half* __restrict__ qkv, const float* __restrict__ mask,
                 const float* __restrict__ rpb, __half* __restrict__ o)
{
    int w = blockIdx.x;
    int h = blockIdx.y;

    __shared__ float q[NTOK][HD];
    __shared__ float k[NTOK][HD];
    __shared__ float v[NTOK][HD];
    __shared__ float s[NTOK][52];

    int tid = threadIdx.x;
    int wid = tid >> 5, lane = tid & 31;
    const __half* base = qkv + (long)w * NTOK * (3 * CH) + h * HD;

    for (int idx = tid; idx < NTOK * (HD / 2); idx += 256) {
        int t = idx >> 4, d2 = idx & 15;
        const __half2* row = (const __half2*)(base + (long)t * (3 * CH)) + d2;
        float2 qv = __half22float2(row[0]);
        float2 kv = __half22float2(row[CH / 2]);
        float2 vv = __half22float2(row[CH]);
        q[t][d2 * 2]     = qv.x * SCALE;
        q[t][d2 * 2 + 1] = qv.y * SCALE;
        k[t][d2 * 2]     = kv.x;
        k[t][d2 * 2 + 1] = kv.y;
        v[t][d2 * 2]     = vv.x;
        v[t][d2 * 2 + 1] = vv.y;
    }
    __syncthreads();

    int wimg = w & (NWIN - 1);
    const float* mrow = mask + (long)wimg * NTOK * NTOK;
    for (int idx = tid; idx < NTOK * NTOK; idx += 256) {
        int t1 = idx / NTOK, t2 = idx % NTOK;
        float acc = 0.0f;
        #pragma unroll
        for (int d = 0; d < HD; d++) acc += q[t1][d] * k[t2][d];
        int di = (t1 / WS) - (t2 / WS) + (WS - 1);
        int dj = (t1 % WS) - (t2 % WS) + (WS - 1);
        acc += rpb[(di * (2 * WS - 1) + dj) * NHEAD + h];
        acc += mrow[idx];
        s[t1][t2] = acc;
    }
    __syncthreads();

    // warp-per-row softmax
    for (int row = wid; row < NTOK; row += 8) {
        float e0 = s[row][lane];
        bool has1 = (lane + 32) < NTOK;
        float e1 = has1 ? s[row][lane + 32] : -1e30f;
        float mx = fmaxf(e0, e1);
        #pragma unroll
        for (int off = 16; off; off >>= 1)
            mx = fmaxf(mx, __shfl_xor_sync(0xffffffff, mx, off));
        float x0 = __expf(e0 - mx);
        float x1 = has1 ? __expf(e1 - mx) : 0.0f;
        float sm = x0 + x1;
        #pragma unroll
        for (int off = 16; off; off >>= 1)
            sm += __shfl_xor_sync(0xffffffff, sm, off);
        float inv = 1.0f / sm;
        s[row][lane] = x0 * inv;
        if (has1) s[row][lane + 32] = x1 * inv;
    }
    __syncthreads();

    __half* ob = o + (long)w * NTOK * CH + h * HD;
    for (int idx = tid; idx < NTOK * (HD / 2); idx += 256) {
        int t = idx >> 4, d2 = idx & 15;
        int d = d2 * 2;
        float a0 = 0.0f, a1 = 0.0f;
        #pragma unroll
        for (int m = 0; m < NTOK; m++) {
            float sm = s[t][m];
            a0 += sm * v[m][d];
            a1 += sm * v[m][d + 1];
        }
        __half2 hp;
        hp.x = __float2half(a0); hp.y = __float2half(a1);
        *(__half2*)(ob + (long)t * CH + d) = hp;
    }
}

// ---------------- LayerNorm -> fp16 ----------------
__global__ __launch_bounds__(128)
void ln_kernel(const float* __restrict__ x, const float* __restrict__ g,
               const float* __restrict__ b, __half* __restrict__ o)
{
    long row = blockIdx.x;
    const float* xr = x + row * CH;
    int tid = threadIdx.x;

    float v0 = xr[tid], v1 = xr[tid + 128], v2 = xr[tid + 256];
    float sum = v0 + v1 + v2;

    __shared__ float red1[4];
    __shared__ float red2[4];
    #pragma unroll
    for (int off = 16; off; off >>= 1) sum += __shfl_xor_sync(0xffffffff, sum, off);
    if ((tid & 31) == 0) red1[tid >> 5] = sum;
    __syncthreads();
    float mu = (red1[0] + red1[1] + red1[2] + red1[3]) * (1.0f / CH);

    float d0 = v0 - mu, d1 = v1 - mu, d2 = v2 - mu;
    float sq = d0 * d0 + d1 * d1 + d2 * d2;
    #pragma unroll
    for (int off = 16; off; off >>= 1) sq += __shfl_xor_sync(0xffffffff, sq, off);
    if ((tid & 31) == 0) red2[tid >> 5] = sq;
    __syncthreads();
    float var = (red2[0] + red2[1] + red2[2] + red2[3]) * (1.0f / CH);
    float rstd = rsqrtf(var + 1e-5f);

    long base = row * CH;
    o[base + tid]       = __float2half(d0 * rstd * g[tid]       + b[tid]);
    o[base + tid + 128] = __float2half(d1 * rstd * g[tid + 128] + b[tid + 128]);
    o[base + tid + 256] = __float2half(d2 * rstd * g[tid + 256] + b[tid + 256]);
}

// ---------------- launch ----------------
extern "C" void kernel_launch(void* const* d_in, const int* in_sizes, int n_in,
                              void* d_out, int out_size)
{
    const float* x      = (const float*)d_in[0];
    const float* mask   = (const float*)d_in[1];
    const float* qkv_w  = (const float*)d_in[2];
    const float* qkv_b  = (const float*)d_in[3];
    const float* proj_w = (const float*)d_in[4];
    const float* proj_b = (const float*)d_in[5];
    const float* rpb    = (const float*)d_in[6];
    const float* n2g    = (const float*)d_in[7];
    const float* n2b    = (const float*)d_in[8];
    const float* fc1w   = (const float*)d_in[9];
    const float* fc1b   = (const float*)d_in[10];
    const float* fc2w   = (const float*)d_in[11];
    const float* fc2b   = (const float*)d_in[12];
    float* out = (float*)d_out;

    void *p;
    #define GSYM(sym, var, ty) cudaGetSymbolAddress(&p, sym); ty* var = (ty*)p;
    GSYM(g_xg, xg, __half)
    GSYM(g_qkv, qkv, __half)
    GSYM(g_at, at, __half)
    GSYM(g_x2, x2, float)
    GSYM(g_hn, hn, __half)
    GSYM(g_hid, hid, __half)
    GSYM(g_map, map, int)
    GSYM(g_wqkv_hi, wqkv_hi, __half) GSYM(g_wqkv_lo, wqkv_lo, __half)
    GSYM(g_wprj_hi, wprj_hi, __half) GSYM(g_wprj_lo, wprj_lo, __half)
    GSYM(g_wf1_hi, wf1_hi, __half) GSYM(g_wf1_lo, wf1_lo, __half)
    GSYM(g_wf2_hi, wf2_hi, __half) GSYM(g_wf2_lo, wf2_lo, __half)
    #undef GSYM

    cudaFuncSetAttribute(gemm_mma<0>, cudaFuncAttributeMaxDynamicSharedMemorySize, SMEM_REQ);
    cudaFuncSetAttribute(gemm_mma<1>, cudaFuncAttributeMaxDynamicSharedMemorySize, SMEM_REQ);
    cudaFuncSetAttribute(gemm_mma<2>, cudaFuncAttributeMaxDynamicSharedMemorySize, SMEM_REQ);
    cudaFuncSetAttribute(gemm_mma<3>, cudaFuncAttributeMaxDynamicSharedMemorySize, SMEM_REQ);

    build_maps_kernel<<<(MROWS + 255) / 256, 256>>>(map);

    long nx = (long)MROWS * CH;
    conv_gather<<<(int)((nx + 255) / 256), 256>>>(x, map, xg);
    conv_wsplit_all<<<(S_ALL + 255) / 256, 256>>>(
        qkv_w, wqkv_hi, wqkv_lo, proj_w, wprj_hi, wprj_lo,
        fc1w, wf1_hi, wf1_lo, fc2w, wf2_hi, wf2_lo);

    // QKV -> fp16 qkv (windowed order)
    gemm_mma<0><<<dim3((3 * CH) / 128, MROWS / 256), 256, SMEM_REQ>>>(
        xg, wqkv_hi, wqkv_lo, qkv_b, nullptr, qkv,
        MROWS, 3 * CH, CH, nullptr, nullptr);

    attn_kernel<<<dim3(BATCH * NWIN, NHEAD), 256>>>(qkv, mask, rpb, at);

    // proj + scatter to image order -> x2 (fp32)
    gemm_mma<1><<<dim3(CH / 128, MROWS / 256), 256, SMEM_REQ>>>(
        at, wprj_hi, wprj_lo, proj_b, x2, nullptr,
        MROWS, CH, CH, map, nullptr);

    ln_kernel<<<MROWS, 128>>>(x2, n2g, n2b, hn);

    // FC1 + GELU -> fp16
    gemm_mma<2><<<dim3(HID / 128, MROWS / 256), 256, SMEM_REQ>>>(
        hn, wf1_hi, wf1_lo, fc1b, nullptr, hid,
        MROWS, HID, CH, nullptr, nullptr);

    // FC2 + residual -> out (fp32)
    gemm_mma<3><<<dim3(CH / 128, MROWS / 256), 256, SMEM_REQ>>>(
        hid, wf2_hi, wf2_lo, fc2b, out, nullptr,
        MROWS, CH, HID, nullptr, x2);
}

// round 15
// speedup vs baseline: 1.1497x; 1.1107x over previous
#include <cuda_runtime.h>
#include <cuda_fp16.h>
#include <math.h>
#include <stdint.h>

// ---------------- problem constants ----------------
#define BATCH 16
#define HW    56
#define CH    384
#define NHEAD 12
#define WS    7
#define NTOK  49
#define HD    32
#define NWIN  64
#define MROWS 50176
#define HID   1536
#define SCALE 0.17677669529663687f

// ---------------- scratch ----------------
__device__ __half g_xg[(long)MROWS * CH];
__device__ __half g_qkv[(long)MROWS * 3 * CH];
__device__ __half g_at[(long)MROWS * CH];
__device__ float  g_x2[(long)MROWS * CH];
__device__ __half g_hn[(long)MROWS * CH];
__device__ __half g_hid[(long)MROWS * HID];
__device__ int    g_map[MROWS];
__device__ __half g_wqkv_hi[3 * CH * CH], g_wqkv_lo[3 * CH * CH];
__device__ __half g_wprj_hi[CH * CH],     g_wprj_lo[CH * CH];
__device__ __half g_wf1_hi[HID * CH],     g_wf1_lo[HID * CH];
__device__ __half g_wf2_hi[CH * HID],     g_wf2_lo[CH * HID];

// ---------------- helpers ----------------
__device__ __forceinline__ uint32_t smem_u32(const void* p) {
    uint32_t a;
    asm("{ .reg .u64 t; cvta.to.shared.u64 t, %1; cvt.u32.u64 %0, t; }" : "=r"(a) : "l"(p));
    return a;
}

#define CP16(dst, src) asm volatile("cp.async.cg.shared.global [%0], [%1], 16;\n" :: "r"(dst), "l"(src))
#define CP_COMMIT()    asm volatile("cp.async.commit_group;\n" ::: "memory")
#define CP_WAIT(n)     asm volatile("cp.async.wait_group %0;\n" :: "n"(n) : "memory")

__device__ __forceinline__ void ldsm4(uint32_t* r, uint32_t addr) {
    asm volatile("ldmatrix.sync.aligned.m8n8.x4.shared.b16 {%0,%1,%2,%3}, [%4];"
                 : "=r"(r[0]), "=r"(r[1]), "=r"(r[2]), "=r"(r[3]) : "r"(addr));
}

__device__ __forceinline__ void mma16816(float* c, const uint32_t* a, uint32_t b0, uint32_t b1) {
    asm volatile(
        "mma.sync.aligned.m16n8k16.row.col.f32.f16.f16.f32 "
        "{%0,%1,%2,%3}, {%4,%5,%6,%7}, {%8,%9}, {%0,%1,%2,%3};\n"
        : "+f"(c[0]), "+f"(c[1]), "+f"(c[2]), "+f"(c[3])
        : "r"(a[0]), "r"(a[1]), "r"(a[2]), "r"(a[3]), "r"(b0), "r"(b1));
}

// ---------------- row permutation map ----------------
__global__ void build_maps_kernel(int* __restrict__ map) {
    int r = blockIdx.x * 256 + threadIdx.x;
    if (r >= MROWS) return;
    int w = r / NTOK, t = r % NTOK;
    int b = w / NWIN, wrem = w % NWIN;
    int wi = wrem / 8, wj = wrem % 8;
    int ti = t / WS, tj = t % WS;
    int h0 = (wi * WS + ti + 3) % HW;
    int w0 = (wj * WS + tj + 3) % HW;
    map[r] = b * (HW * HW) + h0 * HW + w0;
}

// ---------------- conversions ----------------
__device__ __forceinline__ void split_fp16(float v, __half& h, __half& l) {
    h = __float2half(v);
    l = __float2half(v - __half2float(h));
}

#define S_QKV (3 * CH * CH)
#define S_PRJ (CH * CH)
#define S_FC1 (HID * CH)
#define S_FC2 (CH * HID)
#define S_ALL (S_QKV + S_PRJ + S_FC1 + S_FC2)

__global__ void conv_wsplit_all(
    const float* __restrict__ w0, __half* __restrict__ h0, __half* __restrict__ l0,
    const float* __restrict__ w1, __half* __restrict__ h1, __half* __restrict__ l1,
    const float* __restrict__ w2, __half* __restrict__ h2, __half* __restrict__ l2,
    const float* __restrict__ w3, __half* __restrict__ h3, __half* __restrict__ l3)
{
    long i = (long)blockIdx.x * 256 + threadIdx.x;
    if (i >= S_ALL) return;
    const float* src; __half *hi, *lo; long j = i;
    if (j < S_QKV)                 { src = w0; hi = h0; lo = l0; }
    else if ((j -= S_QKV) < S_PRJ) { src = w1; hi = h1; lo = l1; }
    else if ((j -= S_PRJ) < S_FC1) { src = w2; hi = h2; lo = l2; }
    else { j -= S_FC1;               src = w3; hi = h3; lo = l3; }
    __half h, l;
    split_fp16(src[j], h, l);
    hi[j] = h; lo[j] = l;
}

__global__ void conv_gather(const float* __restrict__ x, const int* __restrict__ map,
                            __half* __restrict__ o) {
    long i = (long)blockIdx.x * 256 + threadIdx.x;
    if (i >= (long)MROWS * CH) return;
    long r = i / CH, c = i % CH;
    o[i] = __float2half(x[(long)map[r] * CH + c]);
}

// ---------------- pipelined fp16x2 HMMA GEMM ------------------------------
// C[M,N] = A[M,K] @ (Wh+Wl)[N,K]^T + bias.  CTA tile 256x128 x BK32,
// 4-stage cp.async, 512 threads / 16 warps (4 warps/SMSP for latency hiding).
// warpM = wid&3 (64 rows), warpN = wid>>2 (32 cols).  64 acc regs/thread.
// EPI: 0 fp16 out, 1 fp32 scatter via c_map, 2 GELU->fp16, 3 +resid fp32.

#define NTHREADS 512
#define RSTRIDE 80
#define ATILE_B (256 * RSTRIDE)            // 20480
#define BTILE_B (128 * RSTRIDE)            // 10240
#define STAGE_B (ATILE_B + 2 * BTILE_B)    // 40960
#define STAGES  4
#define SMEM_REQ (STAGES * STAGE_B)        // 163840

__device__ __forceinline__ void load_stage(
    uint32_t sbase, const __half* A, const __half* Bh, const __half* Bl,
    int K, int k0, int tid)
{
    // A: 256 rows x 64B, 2 threads per row
    {
        int r = tid >> 1;
        int q = (tid & 1) * 32;
        uint32_t so = sbase + (uint32_t)(r * RSTRIDE + q);
        const char* pa = (const char*)(A + (size_t)r * K + k0) + q;
        CP16(so,      pa);
        CP16(so + 16, pa + 16);
    }
    // B: threads 0-255 -> Bh rows 0-127, threads 256-511 -> Bl rows 0-127
    {
        int t = tid & 255;
        int r = t >> 1;
        int q = (t & 1) * 32;
        const __half* src = (tid < 256) ? Bh : Bl;
        uint32_t so = sbase + ATILE_B + (tid < 256 ? 0u : (uint32_t)BTILE_B)
                    + (uint32_t)(r * RSTRIDE + q);
        const char* pb = (const char*)(src + (size_t)r * K + k0) + q;
        CP16(so,      pb);
        CP16(so + 16, pb + 16);
    }
}

template <int EPI>
__global__ __launch_bounds__(NTHREADS, 1)
void gemm_mma(const __half* __restrict__ A,
              const __half* __restrict__ Bhw, const __half* __restrict__ Blw,
              const float* __restrict__ bias,
              float* __restrict__ Cf, __half* __restrict__ Ch,
              int M, int N, int K,
              const int* __restrict__ c_map, const float* __restrict__ resid)
{
    extern __shared__ char smem[];
    uint32_t sb = smem_u32(smem);

    int tid = threadIdx.x;
    int wid = tid >> 5, lane = tid & 31;
    int warpM = wid & 3, warpN = wid >> 2;
    int bm = blockIdx.y * 256, bn = blockIdx.x * 128;
    int grp = lane >> 2, tig = lane & 3;

    const __half* pA  = A   + (size_t)bm * K;
    const __half* pBh = Bhw + (size_t)bn * K;
    const __half* pBl = Blw + (size_t)bn * K;

    int a_row = warpM * 64 + (lane & 7) + ((lane >> 3) & 1) * 8;
    uint32_t a_off = (uint32_t)(a_row * RSTRIDE + (lane >> 4) * 16);
    int b_row = warpN * 32 + (lane & 7) + (lane >> 4) * 8;
    uint32_t b_off = (uint32_t)(b_row * RSTRIDE + ((lane >> 3) & 1) * 16);

    float acc[4][4][4];
    #pragma unroll
    for (int a = 0; a < 4; a++)
        #pragma unroll
        for (int b = 0; b < 4; b++)
            #pragma unroll
            for (int c = 0; c < 4; c++) acc[a][b][c] = 0.0f;

    int nk = K / 32;

    #pragma unroll
    for (int s = 0; s < STAGES - 1; s++) {
        if (s < nk) load_stage(sb + s * STAGE_B, pA, pBh, pBl, K, s * 32, tid);
        CP_COMMIT();
    }

    for (int k = 0; k < nk; k++) {
        CP_WAIT(STAGES - 2);
        __syncthreads();

        int kp = k + STAGES - 1;
        if (kp < nk)
            load_stage(sb + (kp % STAGES) * STAGE_B, pA, pBh, pBl, K, kp * 32, tid);
        CP_COMMIT();

        uint32_t st = sb + (k % STAGES) * STAGE_B;
        uint32_t sA = st, sBh = st + ATILE_B, sBl = st + ATILE_B + BTILE_B;

        #pragma unroll
        for (int ks = 0; ks < 2; ks++) {
            uint32_t ko = ks * 32;
            uint32_t af[4][4];
            #pragma unroll
            for (int mf = 0; mf < 4; mf++)
                ldsm4(af[mf], sA + a_off + (uint32_t)(mf * 16 * RSTRIDE) + ko);
            #pragma unroll
            for (int nfp = 0; nfp < 2; nfp++) {
                uint32_t bh[4], bl[4];
                ldsm4(bh, sBh + b_off + (uint32_t)(nfp * 16 * RSTRIDE) + ko);
                ldsm4(bl, sBl + b_off + (uint32_t)(nfp * 16 * RSTRIDE) + ko);
                #pragma unroll
                for (int mf = 0; mf < 4; mf++) {
                    mma16816(acc[mf][2 * nfp],     af[mf], bh[0], bh[1]);
                    mma16816(acc[mf][2 * nfp],     af[mf], bl[0], bl[1]);
                    mma16816(acc[mf][2 * nfp + 1], af[mf], bh[2], bh[3]);
                    mma16816(acc[mf][2 * nfp + 1], af[mf], bl[2], bl[3]);
                }
            }
        }
        __syncthreads();
    }

    // epilogue: warp covers rows [warpM*64, +64), cols [warpN*32, +32)
    #pragma unroll
    for (int mf = 0; mf < 4; mf++) {
        int mbase = bm + warpM * 64 + mf * 16 + grp;
        #pragma unroll
        for (int nf = 0; nf < 4; nf++) {
            int n0 = bn + warpN * 32 + nf * 8 + 2 * tig;
            float bi0 = bias[n0], bi1 = bias[n0 + 1];
            #pragma unroll
            for (int half_ = 0; half_ < 2; half_++) {
                int m = mbase + half_ * 8;
                float v0 = acc[mf][nf][half_ * 2 + 0] + bi0;
                float v1 = acc[mf][nf][half_ * 2 + 1] + bi1;
                if (EPI == 0) {
                    __half2 hp;
                    hp.x = __float2half(v0); hp.y = __float2half(v1);
                    *(__half2*)(Ch + (size_t)m * N + n0) = hp;
                } else if (EPI == 1) {
                    size_t orow = (size_t)c_map[m];
                    Cf[orow * N + n0]     = v0;
                    Cf[orow * N + n0 + 1] = v1;
                } else if (EPI == 2) {
                    v0 = 0.5f * v0 * (1.0f + erff(v0 * 0.70710678118654752f));
                    v1 = 0.5f * v1 * (1.0f + erff(v1 * 0.70710678118654752f));
                    __half2 hp;
                    hp.x = __float2half(v0); hp.y = __float2half(v1);
                    *(__half2*)(Ch + (size_t)m * N + n0) = hp;
                } else {
                    size_t rb = (size_t)m * N + n0;
                    Cf[rb]     = v0 + resid[rb];
                    Cf[rb + 1] = v1 + resid[rb + 1];
                }
            }
        }
    }
}

// ---------------- windowed attention (fp16 in/out, parallel softmax) -------
__global__ __launch_bounds__(256)
void attn_kernel(const __half* __restrict__ qkv, const float* __restrict__ mask,
                 const float* __restrict__ rpb, __half* __restrict__ o)
{
    int w = blockIdx.x;
    int h = blockIdx.y;

    __shared__ float q[NTOK][HD];
    __shared__ float k[NTOK][HD];
    __shared__ float v[NTOK][HD];
    __shared__ float s[NTOK][52];

    int tid = threadIdx.x;
    int wid = tid >> 5, lane = tid & 31;
    const __half* base = qkv + (long)w * NTOK * (3 * CH) + h * HD;

    for (int idx = tid; idx < NTOK * (HD / 2); idx += 256) {
        int t = idx >> 4, d2 = idx & 15;
        const __half2* row = (const __half2*)(base + (long)t * (3 * CH)) + d2;
        float2 qv = __half22float2(row[0]);
        float2 kv = __half22float2(row[CH / 2]);
        float2 vv = __half22float2(row[CH]);
        q[t][d2 * 2]     = qv.x * SCALE;
        q[t][d2 * 2 + 1] = qv.y * SCALE;
        k[t][d2 * 2]     = kv.x;
        k[t][d2 * 2 + 1] = kv.y;
        v[t][d2 * 2]     = vv.x;
        v[t][d2 * 2 + 1] = vv.y;
    }
    __syncthreads();

    int wimg = w & (NWIN - 1);
    const float* mrow = mask + (long)wimg * NTOK * NTOK;
    for (int idx = tid; idx < NTOK * NTOK; idx += 256) {
        int t1 = idx / NTOK, t2 = idx % NTOK;
        float acc = 0.0f;
        #pragma unroll
        for (int d = 0; d < HD; d++) acc += q[t1][d] * k[t2][d];
        int di = (t1 / WS) - (t2 / WS) + (WS - 1);
        int dj = (t1 % WS) - (t2 % WS) + (WS - 1);
        acc += rpb[(di * (2 * WS - 1) + dj) * NHEAD + h];
        acc += mrow[idx];
        s[t1][t2] = acc;
    }
    __syncthreads();

    for (int row = wid; row < NTOK; row += 8) {
        float e0 = s[row][lane];
        bool has1 = (lane + 32) < NTOK;
        float e1 = has1 ? s[row][lane + 32] : -1e30f;
        float mx = fmaxf(e0, e1);
        #pragma unroll
        for (int off = 16; off; off >>= 1)
            mx = fmaxf(mx, __shfl_xor_sync(0xffffffff, mx, off));
        float x0 = __expf(e0 - mx);
        float x1 = has1 ? __expf(e1 - mx) : 0.0f;
        float sm = x0 + x1;
        #pragma unroll
        for (int off = 16; off; off >>= 1)
            sm += __shfl_xor_sync(0xffffffff, sm, off);
        float inv = 1.0f / sm;
        s[row][lane] = x0 * inv;
        if (has1) s[row][lane + 32] = x1 * inv;
    }
    __syncthreads();

    __half* ob = o + (long)w * NTOK * CH + h * HD;
    for (int idx = tid; idx < NTOK * (HD / 2); idx += 256) {
        int t = idx >> 4, d2 = idx & 15;
        int d = d2 * 2;
        float a0 = 0.0f, a1 = 0.0f;
        #pragma unroll
        for (int m = 0; m < NTOK; m++) {
            float sm = s[t][m];
            a0 += sm * v[m][d];
            a1 += sm * v[m][d + 1];
        }
        __half2 hp;
        hp.x = __float2half(a0); hp.y = __float2half(a1);
        *(__half2*)(ob + (long)t * CH + d) = hp;
    }
}

// ---------------- LayerNorm -> fp16 ----------------
__global__ __launch_bounds__(128)
void ln_kernel(const float* __restrict__ x, const float* __restrict__ g,
               const float* __restrict__ b, __half* __restrict__ o)
{
    long row = blockIdx.x;
    const float* xr = x + row * CH;
    int tid = threadIdx.x;

    float v0 = xr[tid], v1 = xr[tid + 128], v2 = xr[tid + 256];
    float sum = v0 + v1 + v2;

    __shared__ float red1[4];
    __shared__ float red2[4];
    #pragma unroll
    for (int off = 16; off; off >>= 1) sum += __shfl_xor_sync(0xffffffff, sum, off);
    if ((tid & 31) == 0) red1[tid >> 5] = sum;
    __syncthreads();
    float mu = (red1[0] + red1[1] + red1[2] + red1[3]) * (1.0f / CH);

    float d0 = v0 - mu, d1 = v1 - mu, d2 = v2 - mu;
    float sq = d0 * d0 + d1 * d1 + d2 * d2;
    #pragma unroll
    for (int off = 16; off; off >>= 1) sq += __shfl_xor_sync(0xffffffff, sq, off);
    if ((tid & 31) == 0) red2[tid >> 5] = sq;
    __syncthreads();
    float var = (red2[0] + red2[1] + red2[2] + red2[3]) * (1.0f / CH);
    float rstd = rsqrtf(var + 1e-5f);

    long base = row * CH;
    o[base + tid]       = __float2half(d0 * rstd * g[tid]       + b[tid]);
    o[base + tid + 128] = __float2half(d1 * rstd * g[tid + 128] + b[tid + 128]);
    o[base + tid + 256] = __float2half(d2 * rstd * g[tid + 256] + b[tid + 256]);
}

// ---------------- launch ----------------
extern "C" void kernel_launch(void* const* d_in, const int* in_sizes, int n_in,
                              void* d_out, int out_size)
{
    const float* x      = (const float*)d_in[0];
    const float* mask   = (const float*)d_in[1];
    const float* qkv_w  = (const float*)d_in[2];
    const float* qkv_b  = (const float*)d_in[3];
    const float* proj_w = (const float*)d_in[4];
    const float* proj_b = (const float*)d_in[5];
    const float* rpb    = (const float*)d_in[6];
    const float* n2g    = (const float*)d_in[7];
    const float* n2b    = (const float*)d_in[8];
    const float* fc1w   = (const float*)d_in[9];
    const float* fc1b   = (const float*)d_in[10];
    const float* fc2w   = (const float*)d_in[11];
    const float* fc2b   = (const float*)d_in[12];
    float* out = (float*)d_out;

    void *p;
    #define GSYM(sym, var, ty) cudaGetSymbolAddress(&p, sym); ty* var = (ty*)p;
    GSYM(g_xg, xg, __half)
    GSYM(g_qkv, qkv, __half)
    GSYM(g_at, at, __half)
    GSYM(g_x2, x2, float)
    GSYM(g_hn, hn, __half)
    GSYM(g_hid, hid, __half)
    GSYM(g_map, map, int)
    GSYM(g_wqkv_hi, wqkv_hi, __half) GSYM(g_wqkv_lo, wqkv_lo, __half)
    GSYM(g_wprj_hi, wprj_hi, __half) GSYM(g_wprj_lo, wprj_lo, __half)
    GSYM(g_wf1_hi, wf1_hi, __half) GSYM(g_wf1_lo, wf1_lo, __half)
    GSYM(g_wf2_hi, wf2_hi, __half) GSYM(g_wf2_lo, wf2_lo, __half)
    #undef GSYM

    cudaFuncSetAttribute(gemm_mma<0>, cudaFuncAttributeMaxDynamicSharedMemorySize, SMEM_REQ);
    cudaFuncSetAttribute(gemm_mma<1>, cudaFuncAttributeMaxDynamicSharedMemorySize, SMEM_REQ);
    cudaFuncSetAttribute(gemm_mma<2>, cudaFuncAttributeMaxDynamicSharedMemorySize, SMEM_REQ);
    cudaFuncSetAttribute(gemm_mma<3>, cudaFuncAttributeMaxDynamicSharedMemorySize, SMEM_REQ);

    build_maps_kernel<<<(MROWS + 255) / 256, 256>>>(map);

    long nx = (long)MROWS * CH;
    conv_gather<<<(int)((nx + 255) / 256), 256>>>(x, map, xg);
    conv_wsplit_all<<<(S_ALL + 255) / 256, 256>>>(
        qkv_w, wqkv_hi, wqkv_lo, proj_w, wprj_hi, wprj_lo,
        fc1w, wf1_hi, wf1_lo, fc2w, wf2_hi, wf2_lo);

    // QKV -> fp16 qkv (windowed order)
    gemm_mma<0><<<dim3((3 * CH) / 128, MROWS / 256), NTHREADS, SMEM_REQ>>>(
        xg, wqkv_hi, wqkv_lo, qkv_b, nullptr, qkv,
        MROWS, 3 * CH, CH, nullptr, nullptr);

    attn_kernel<<<dim3(BATCH * NWIN, NHEAD), 256>>>(qkv, mask, rpb, at);

    // proj + scatter to image order -> x2 (fp32)
    gemm_mma<1><<<dim3(CH / 128, MROWS / 256), NTHREADS, SMEM_REQ>>>(
        at, wprj_hi, wprj_lo, proj_b, x2, nullptr,
        MROWS, CH, CH, map, nullptr);

    ln_kernel<<<MROWS, 128>>>(x2, n2g, n2b, hn);

    // FC1 + GELU -> fp16
    gemm_mma<2><<<dim3(HID / 128, MROWS / 256), NTHREADS, SMEM_REQ>>>(
        hn, wf1_hi, wf1_lo, fc1b, nullptr, hid,
        MROWS, HID, CH, nullptr, nullptr);

    // FC2 + residual -> out (fp32)
    gemm_mma<3><<<dim3(CH / 128, MROWS / 256), NTHREADS, SMEM_REQ>>>(
        hid, wf2_hi, wf2_lo, fc2b, out, nullptr,
        MROWS, CH, HID, nullptr, x2);
}

// round 16
// speedup vs baseline: 1.1543x; 1.0040x over previous
#include <cuda_runtime.h>
#include <cuda_fp16.h>
#include <math.h>
#include <stdint.h>

// ---------------- problem constants ----------------
#define BATCH 16
#define HW    56
#define CH    384
#define NHEAD 12
#define WS    7
#define NTOK  49
#define HD    32
#define NWIN  64
#define MROWS 50176
#define HID   1536
#define SCALE 0.17677669529663687f

// ---------------- scratch ----------------
__device__ __half g_xg[(long)MROWS * CH];
__device__ __half g_qkv[(long)MROWS * 3 * CH];
__device__ __half g_at[(long)MROWS * CH];
__device__ float  g_x2[(long)MROWS * CH];
__device__ __half g_hn[(long)MROWS * CH];
__device__ __half g_hid[(long)MROWS * HID];
__device__ int    g_map[MROWS];
__device__ __half g_wqkv_hi[3 * CH * CH], g_wqkv_lo[3 * CH * CH];
__device__ __half g_wprj_hi[CH * CH],     g_wprj_lo[CH * CH];
__device__ __half g_wf1_hi[HID * CH],     g_wf1_lo[HID * CH];
__device__ __half g_wf2_hi[CH * HID],     g_wf2_lo[CH * HID];

// ---------------- helpers ----------------
__device__ __forceinline__ uint32_t smem_u32(const void* p) {
    uint32_t a;
    asm("{ .reg .u64 t; cvta.to.shared.u64 t, %1; cvt.u32.u64 %0, t; }" : "=r"(a) : "l"(p));
    return a;
}

#define CP16(dst, src) asm volatile("cp.async.cg.shared.global [%0], [%1], 16;\n" :: "r"(dst), "l"(src))
#define CP_COMMIT()    asm volatile("cp.async.commit_group;\n" ::: "memory")
#define CP_WAIT(n)     asm volatile("cp.async.wait_group %0;\n" :: "n"(n) : "memory")

__device__ __forceinline__ void ldsm4(uint32_t* r, uint32_t addr) {
    asm volatile("ldmatrix.sync.aligned.m8n8.x4.shared.b16 {%0,%1,%2,%3}, [%4];"
                 : "=r"(r[0]), "=r"(r[1]), "=r"(r[2]), "=r"(r[3]) : "r"(addr));
}

__device__ __forceinline__ void mma16816(float* c, const uint32_t* a, uint32_t b0, uint32_t b1) {
    asm volatile(
        "mma.sync.aligned.m16n8k16.row.col.f32.f16.f16.f32 "
        "{%0,%1,%2,%3}, {%4,%5,%6,%7}, {%8,%9}, {%0,%1,%2,%3};\n"
        : "+f"(c[0]), "+f"(c[1]), "+f"(c[2]), "+f"(c[3])
        : "r"(a[0]), "r"(a[1]), "r"(a[2]), "r"(a[3]), "r"(b0), "r"(b1));
}

// ---------------- row permutation map ----------------
__global__ void build_maps_kernel(int* __restrict__ map) {
    int r = blockIdx.x * 256 + threadIdx.x;
    if (r >= MROWS) return;
    int w = r / NTOK, t = r % NTOK;
    int b = w / NWIN, wrem = w % NWIN;
    int wi = wrem / 8, wj = wrem % 8;
    int ti = t / WS, tj = t % WS;
    int h0 = (wi * WS + ti + 3) % HW;
    int w0 = (wj * WS + tj + 3) % HW;
    map[r] = b * (HW * HW) + h0 * HW + w0;
}

// ---------------- conversions ----------------
__device__ __forceinline__ void split_fp16(float v, __half& h, __half& l) {
    h = __float2half(v);
    l = __float2half(v - __half2float(h));
}

#define S_QKV (3 * CH * CH)
#define S_PRJ (CH * CH)
#define S_FC1 (HID * CH)
#define S_FC2 (CH * HID)
#define S_ALL (S_QKV + S_PRJ + S_FC1 + S_FC2)

__global__ void conv_wsplit_all(
    const float* __restrict__ w0, __half* __restrict__ h0, __half* __restrict__ l0,
    const float* __restrict__ w1, __half* __restrict__ h1, __half* __restrict__ l1,
    const float* __restrict__ w2, __half* __restrict__ h2, __half* __restrict__ l2,
    const float* __restrict__ w3, __half* __restrict__ h3, __half* __restrict__ l3)
{
    long i = (long)blockIdx.x * 256 + threadIdx.x;
    if (i >= S_ALL) return;
    const float* src; __half *hi, *lo; long j = i;
    if (j < S_QKV)                 { src = w0; hi = h0; lo = l0; }
    else if ((j -= S_QKV) < S_PRJ) { src = w1; hi = h1; lo = l1; }
    else if ((j -= S_PRJ) < S_FC1) { src = w2; hi = h2; lo = l2; }
    else { j -= S_FC1;               src = w3; hi = h3; lo = l3; }
    __half h, l;
    split_fp16(src[j], h, l);
    hi[j] = h; lo[j] = l;
}

__global__ void conv_gather(const float* __restrict__ x, const int* __restrict__ map,
                            __half* __restrict__ o) {
    long i = (long)blockIdx.x * 256 + threadIdx.x;
    if (i >= (long)MROWS * CH) return;
    long r = i / CH, c = i % CH;
    o[i] = __float2half(x[(long)map[r] * CH + c]);
}

// ---------------- pipelined fp16x2 HMMA GEMM ------------------------------
// C[M,N] = A[M,K] @ (Wh+Wl)[N,K]^T + bias.  CTA tile 128x128 x BK32,
// 3-stage cp.async, 256 threads / 8 warps, TWO CTAs per SM (launch_bounds
// (256,2): 128 regs/thread, 92KB smem/CTA).  warpM = wid&1, warpN = wid>>1.
// EPI: 0 fp16 out, 1 fp32 scatter via c_map, 2 GELU->fp16, 3 +resid fp32.

#define RSTRIDE 80
#define TILE_B  (128 * RSTRIDE)            // 10240
#define STAGE_B (3 * TILE_B)               // A, Bh, Bl = 30720
#define STAGES  3
#define SMEM_REQ (STAGES * STAGE_B)        // 92160 -> 2 CTAs/SM

__device__ __forceinline__ void load_stage(
    uint32_t sbase, const __half* A, const __half* Bh, const __half* Bl,
    int K, int k0, int tid)
{
    int row = tid >> 1;
    int c0 = (tid & 1) * 32;
    uint32_t so = (uint32_t)(row * RSTRIDE + c0);
    size_t go = (size_t)row * K + k0;
    const char* pa = (const char*)(A + go) + c0;
    const char* pb = (const char*)(Bh + go) + c0;
    const char* pc = (const char*)(Bl + go) + c0;
    CP16(sbase + so,                    pa);
    CP16(sbase + so + 16,               pa + 16);
    CP16(sbase + TILE_B + so,           pb);
    CP16(sbase + TILE_B + so + 16,      pb + 16);
    CP16(sbase + 2 * TILE_B + so,       pc);
    CP16(sbase + 2 * TILE_B + so + 16,  pc + 16);
}

template <int EPI>
__global__ __launch_bounds__(256, 2)
void gemm_mma(const __half* __restrict__ A,
              const __half* __restrict__ Bhw, const __half* __restrict__ Blw,
              const float* __restrict__ bias,
              float* __restrict__ Cf, __half* __restrict__ Ch,
              int M, int N, int K,
              const int* __restrict__ c_map, const float* __restrict__ resid)
{
    extern __shared__ char smem[];
    uint32_t sb = smem_u32(smem);

    int tid = threadIdx.x;
    int wid = tid >> 5, lane = tid & 31;
    int warpM = wid & 1, warpN = wid >> 1;
    int bm = blockIdx.y * 128, bn = blockIdx.x * 128;
    int grp = lane >> 2, tig = lane & 3;

    const __half* pA  = A   + (size_t)bm * K;
    const __half* pBh = Bhw + (size_t)bn * K;
    const __half* pBl = Blw + (size_t)bn * K;

    int a_row = warpM * 64 + (lane & 7) + ((lane >> 3) & 1) * 8;
    uint32_t a_off = (uint32_t)(a_row * RSTRIDE + (lane >> 4) * 16);
    int b_row = warpN * 32 + (lane & 7) + (lane >> 4) * 8;
    uint32_t b_off = (uint32_t)(b_row * RSTRIDE + ((lane >> 3) & 1) * 16);

    float acc[4][4][4];
    #pragma unroll
    for (int a = 0; a < 4; a++)
        #pragma unroll
        for (int b = 0; b < 4; b++)
            #pragma unroll
            for (int c = 0; c < 4; c++) acc[a][b][c] = 0.0f;

    int nk = K / 32;

    load_stage(sb, pA, pBh, pBl, K, 0, tid);
    CP_COMMIT();
    load_stage(sb + STAGE_B, pA, pBh, pBl, K, 32, tid);
    CP_COMMIT();

    for (int k = 0; k < nk; k++) {
        CP_WAIT(1);
        __syncthreads();

        int kp = k + 2;
        if (kp < nk)
            load_stage(sb + (kp % STAGES) * STAGE_B, pA, pBh, pBl, K, kp * 32, tid);
        CP_COMMIT();

        uint32_t st = sb + (k % STAGES) * STAGE_B;
        uint32_t sA = st, sBh = st + TILE_B, sBl = st + 2 * TILE_B;

        #pragma unroll
        for (int ks = 0; ks < 2; ks++) {
            uint32_t ko = ks * 32;
            uint32_t af[4][4];
            #pragma unroll
            for (int mf = 0; mf < 4; mf++)
                ldsm4(af[mf], sA + a_off + (uint32_t)(mf * 16 * RSTRIDE) + ko);
            #pragma unroll
            for (int nfp = 0; nfp < 2; nfp++) {
                uint32_t bh[4], bl[4];
                ldsm4(bh, sBh + b_off + (uint32_t)(nfp * 16 * RSTRIDE) + ko);
                ldsm4(bl, sBl + b_off + (uint32_t)(nfp * 16 * RSTRIDE) + ko);
                #pragma unroll
                for (int mf = 0; mf < 4; mf++) {
                    mma16816(acc[mf][2 * nfp],     af[mf], bh[0], bh[1]);
                    mma16816(acc[mf][2 * nfp],     af[mf], bl[0], bl[1]);
                    mma16816(acc[mf][2 * nfp + 1], af[mf], bh[2], bh[3]);
                    mma16816(acc[mf][2 * nfp + 1], af[mf], bl[2], bl[3]);
                }
            }
        }
        __syncthreads();
    }

    // epilogue: warp covers rows [warpM*64, +64), cols [warpN*32, +32)
    #pragma unroll
    for (int mf = 0; mf < 4; mf++) {
        int mbase = bm + warpM * 64 + mf * 16 + grp;
        #pragma unroll
        for (int nf = 0; nf < 4; nf++) {
            int n0 = bn + warpN * 32 + nf * 8 + 2 * tig;
            float bi0 = bias[n0], bi1 = bias[n0 + 1];
            #pragma unroll
            for (int half_ = 0; half_ < 2; half_++) {
                int m = mbase + half_ * 8;
                float v0 = acc[mf][nf][half_ * 2 + 0] + bi0;
                float v1 = acc[mf][nf][half_ * 2 + 1] + bi1;
                if (EPI == 0) {
                    __half2 hp;
                    hp.x = __float2half(v0); hp.y = __float2half(v1);
                    *(__half2*)(Ch + (size_t)m * N + n0) = hp;
                } else if (EPI == 1) {
                    size_t orow = (size_t)c_map[m];
                    Cf[orow * N + n0]     = v0;
                    Cf[orow * N + n0 + 1] = v1;
                } else if (EPI == 2) {
                    v0 = 0.5f * v0 * (1.0f + erff(v0 * 0.70710678118654752f));
                    v1 = 0.5f * v1 * (1.0f + erff(v1 * 0.70710678118654752f));
                    __half2 hp;
                    hp.x = __float2half(v0); hp.y = __float2half(v1);
                    *(__half2*)(Ch + (size_t)m * N + n0) = hp;
                } else {
                    size_t rb = (size_t)m * N + n0;
                    Cf[rb]     = v0 + resid[rb];
                    Cf[rb + 1] = v1 + resid[rb + 1];
                }
            }
        }
    }
}

// ---------------- windowed attention (fp16 in/out, parallel softmax) -------
__global__ __launch_bounds__(256)
void attn_kernel(const __half* __restrict__ qkv, const float* __restrict__ mask,
                 const float* __restrict__ rpb, __half* __restrict__ o)
{
    int w = blockIdx.x;
    int h = blockIdx.y;

    __shared__ float q[NTOK][HD];
    __shared__ float k[NTOK][HD];
    __shared__ float v[NTOK][HD];
    __shared__ float s[NTOK][52];

    int tid = threadIdx.x;
    int wid = tid >> 5, lane = tid & 31;
    const __half* base = qkv + (long)w * NTOK * (3 * CH) + h * HD;

    for (int idx = tid; idx < NTOK * (HD / 2); idx += 256) {
        int t = idx >> 4, d2 = idx & 15;
        const __half2* row = (const __half2*)(base + (long)t * (3 * CH)) + d2;
        float2 qv = __half22float2(row[0]);
        float2 kv = __half22float2(row[CH / 2]);
        float2 vv = __half22float2(row[CH]);
        q[t][d2 * 2]     = qv.x * SCALE;
        q[t][d2 * 2 + 1] = qv.y * SCALE;
        k[t][d2 * 2]     = kv.x;
        k[t][d2 * 2 + 1] = kv.y;
        v[t][d2 * 2]     = vv.x;
        v[t][d2 * 2 + 1] = vv.y;
    }
    __syncthreads();

    int wimg = w & (NWIN - 1);
    const float* mrow = mask + (long)wimg * NTOK * NTOK;
    for (int idx = tid; idx < NTOK * NTOK; idx += 256) {
        int t1 = idx / NTOK, t2 = idx % NTOK;
        float acc = 0.0f;
        #pragma unroll
        for (int d = 0; d < HD; d++) acc += q[t1][d] * k[t2][d];
        int di = (t1 / WS) - (t2 / WS) + (WS - 1);
        int dj = (t1 % WS) - (t2 % WS) + (WS - 1);
        acc += rpb[(di * (2 * WS - 1) + dj) * NHEAD + h];
        acc += mrow[idx];
        s[t1][t2] = acc;
    }
    __syncthreads();

    for (int row = wid; row < NTOK; row += 8) {
        float e0 = s[row][lane];
        bool has1 = (lane + 32) < NTOK;
        float e1 = has1 ? s[row][lane + 32] : -1e30f;
        float mx = fmaxf(e0, e1);
        #pragma unroll
        for (int off = 16; off; off >>= 1)
            mx = fmaxf(mx, __shfl_xor_sync(0xffffffff, mx, off));
        float x0 = __expf(e0 - mx);
        float x1 = has1 ? __expf(e1 - mx) : 0.0f;
        float sm = x0 + x1;
        #pragma unroll
        for (int off = 16; off; off >>= 1)
            sm += __shfl_xor_sync(0xffffffff, sm, off);
        float inv = 1.0f / sm;
        s[row][lane] = x0 * inv;
        if (has1) s[row][lane + 32] = x1 * inv;
    }
    __syncthreads();

    __half* ob = o + (long)w * NTOK * CH + h * HD;
    for (int idx = tid; idx < NTOK * (HD / 2); idx += 256) {
        int t = idx >> 4, d2 = idx & 15;
        int d = d2 * 2;
        float a0 = 0.0f, a1 = 0.0f;
        #pragma unroll
        for (int m = 0; m < NTOK; m++) {
            float sm = s[t][m];
            a0 += sm * v[m][d];
            a1 += sm * v[m][d + 1];
        }
        __half2 hp;
        hp.x = __float2half(a0); hp.y = __float2half(a1);
        *(__half2*)(ob + (long)t * CH + d) = hp;
    }
}

// ---------------- LayerNorm -> fp16 ----------------
__global__ __launch_bounds__(128)
void ln_kernel(const float* __restrict__ x, const float* __restrict__ g,
               const float* __restrict__ b, __half* __restrict__ o)
{
    long row = blockIdx.x;
    const float* xr = x + row * CH;
    int tid = threadIdx.x;

    float v0 = xr[tid], v1 = xr[tid + 128], v2 = xr[tid + 256];
    float sum = v0 + v1 + v2;

    __shared__ float red1[4];
    __shared__ float red2[4];
    #pragma unroll
    for (int off = 16; off; off >>= 1) sum += __shfl_xor_sync(0xffffffff, sum, off);
    if ((tid & 31) == 0) red1[tid >> 5] = sum;
    __syncthreads();
    float mu = (red1[0] + red1[1] + red1[2] + red1[3]) * (1.0f / CH);

    float d0 = v0 - mu, d1 = v1 - mu, d2 = v2 - mu;
    float sq = d0 * d0 + d1 * d1 + d2 * d2;
    #pragma unroll
    for (int off = 16; off; off >>= 1) sq += __shfl_xor_sync(0xffffffff, sq, off);
    if ((tid & 31) == 0) red2[tid >> 5] = sq;
    __syncthreads();
    float var = (red2[0] + red2[1] + red2[2] + red2[3]) * (1.0f / CH);
    float rstd = rsqrtf(var + 1e-5f);

    long base = row * CH;
    o[base + tid]       = __float2half(d0 * rstd * g[tid]       + b[tid]);
    o[base + tid + 128] = __float2half(d1 * rstd * g[tid + 128] + b[tid + 128]);
    o[base + tid + 256] = __float2half(d2 * rstd * g[tid + 256] + b[tid + 256]);
}

// ---------------- launch ----------------
extern "C" void kernel_launch(void* const* d_in, const int* in_sizes, int n_in,
                              void* d_out, int out_size)
{
    const float* x      = (const float*)d_in[0];
    const float* mask   = (const float*)d_in[1];
    const float* qkv_w  = (const float*)d_in[2];
    const float* qkv_b  = (const float*)d_in[3];
    const float* proj_w = (const float*)d_in[4];
    const float* proj_b = (const float*)d_in[5];
    const float* rpb    = (const float*)d_in[6];
    const float* n2g    = (const float*)d_in[7];
    const float* n2b    = (const float*)d_in[8];
    const float* fc1w   = (const float*)d_in[9];
    const float* fc1b   = (const float*)d_in[10];
    const float* fc2w   = (const float*)d_in[11];
    const float* fc2b   = (const float*)d_in[12];
    float* out = (float*)d_out;

    void *p;
    #define GSYM(sym, var, ty) cudaGetSymbolAddress(&p, sym); ty* var = (ty*)p;
    GSYM(g_xg, xg, __half)
    GSYM(g_qkv, qkv, __half)
    GSYM(g_at, at, __half)
    GSYM(g_x2, x2, float)
    GSYM(g_hn, hn, __half)
    GSYM(g_hid, hid, __half)
    GSYM(g_map, map, int)
    GSYM(g_wqkv_hi, wqkv_hi, __half) GSYM(g_wqkv_lo, wqkv_lo, __half)
    GSYM(g_wprj_hi, wprj_hi, __half) GSYM(g_wprj_lo, wprj_lo, __half)
    GSYM(g_wf1_hi, wf1_hi, __half) GSYM(g_wf1_lo, wf1_lo, __half)
    GSYM(g_wf2_hi, wf2_hi, __half) GSYM(g_wf2_lo, wf2_lo, __half)
    #undef GSYM

    cudaFuncSetAttribute(gemm_mma<0>, cudaFuncAttributeMaxDynamicSharedMemorySize, SMEM_REQ);
    cudaFuncSetAttribute(gemm_mma<1>, cudaFuncAttributeMaxDynamicSharedMemorySize, SMEM_REQ);
    cudaFuncSetAttribute(gemm_mma<2>, cudaFuncAttributeMaxDynamicSharedMemorySize, SMEM_REQ);
    cudaFuncSetAttribute(gemm_mma<3>, cudaFuncAttributeMaxDynamicSharedMemorySize, SMEM_REQ);

    build_maps_kernel<<<(MROWS + 255) / 256, 256>>>(map);

    long nx = (long)MROWS * CH;
    conv_gather<<<(int)((nx + 255) / 256), 256>>>(x, map, xg);
    conv_wsplit_all<<<(S_ALL + 255) / 256, 256>>>(
        qkv_w, wqkv_hi, wqkv_lo, proj_w, wprj_hi, wprj_lo,
        fc1w, wf1_hi, wf1_lo, fc2w, wf2_hi, wf2_lo);

    // QKV -> fp16 qkv (windowed order)
    gemm_mma<0><<<dim3((3 * CH) / 128, MROWS / 128), 256, SMEM_REQ>>>(
        xg, wqkv_hi, wqkv_lo, qkv_b, nullptr, qkv,
        MROWS, 3 * CH, CH, nullptr, nullptr);

    attn_kernel<<<dim3(BATCH * NWIN, NHEAD), 256>>>(qkv, mask, rpb, at);

    // proj + scatter to image order -> x2 (fp32)
    gemm_mma<1><<<dim3(CH / 128, MROWS / 128), 256, SMEM_REQ>>>(
        at, wprj_hi, wprj_lo, proj_b, x2, nullptr,
        MROWS, CH, CH, map, nullptr);

    ln_kernel<<<MROWS, 128>>>(x2, n2g, n2b, hn);

    // FC1 + GELU -> fp16
    gemm_mma<2><<<dim3(HID / 128, MROWS / 128), 256, SMEM_REQ>>>(
        hn, wf1_hi, wf1_lo, fc1b, nullptr, hid,
        MROWS, HID, CH, nullptr, nullptr);

    // FC2 + residual -> out (fp32)
    gemm_mma<3><<<dim3(CH / 128, MROWS / 128), 256, SMEM_REQ>>>(
        hid, wf2_hi, wf2_lo, fc2b, out, nullptr,
        MROWS, CH, HID, nullptr, x2);
}

// round 17
// speedup vs baseline: 1.1558x; 1.0013x over previous
#include <cuda_runtime.h>
#include <cuda_fp16.h>
#include <math.h>
#include <stdint.h>

// ---------------- problem constants ----------------
#define BATCH 16
#define HW    56
#define CH    384
#define NHEAD 12
#define WS    7
#define NTOK  49
#define HD    32
#define NWIN  64
#define MROWS 50176
#define HID   1536
#define SCALE 0.17677669529663687f

// ---------------- scratch ----------------
__device__ __half g_xg[(long)MROWS * CH];
__device__ __half g_qkv[(long)MROWS * 3 * CH];
__device__ __half g_at[(long)MROWS * CH];
__device__ float  g_x2[(long)MROWS * CH];
__device__ __half g_hn[(long)MROWS * CH];
__device__ __half g_hid[(long)MROWS * HID];
__device__ int    g_map[MROWS];
__device__ __half g_wqkv_hi[3 * CH * CH], g_wqkv_lo[3 * CH * CH];
__device__ __half g_wprj_hi[CH * CH],     g_wprj_lo[CH * CH];
__device__ __half g_wf1_hi[HID * CH],     g_wf1_lo[HID * CH];
__device__ __half g_wf2_hi[CH * HID],     g_wf2_lo[CH * HID];

// ---------------- helpers ----------------
__device__ __forceinline__ uint32_t smem_u32(const void* p) {
    uint32_t a;
    asm("{ .reg .u64 t; cvta.to.shared.u64 t, %1; cvt.u32.u64 %0, t; }" : "=r"(a) : "l"(p));
    return a;
}

#define CP16(dst, src) asm volatile("cp.async.cg.shared.global [%0], [%1], 16;\n" :: "r"(dst), "l"(src))
#define CP_COMMIT()    asm volatile("cp.async.commit_group;\n" ::: "memory")
#define CP_WAIT(n)     asm volatile("cp.async.wait_group %0;\n" :: "n"(n) : "memory")

__device__ __forceinline__ void ldsm4(uint32_t* r, uint32_t addr) {
    asm volatile("ldmatrix.sync.aligned.m8n8.x4.shared.b16 {%0,%1,%2,%3}, [%4];"
                 : "=r"(r[0]), "=r"(r[1]), "=r"(r[2]), "=r"(r[3]) : "r"(addr));
}

__device__ __forceinline__ void mma16816(float* c, const uint32_t* a, uint32_t b0, uint32_t b1) {
    asm volatile(
        "mma.sync.aligned.m16n8k16.row.col.f32.f16.f16.f32 "
        "{%0,%1,%2,%3}, {%4,%5,%6,%7}, {%8,%9}, {%0,%1,%2,%3};\n"
        : "+f"(c[0]), "+f"(c[1]), "+f"(c[2]), "+f"(c[3])
        : "r"(a[0]), "r"(a[1]), "r"(a[2]), "r"(a[3]), "r"(b0), "r"(b1));
}

// ---------------- row permutation map ----------------
__global__ void build_maps_kernel(int* __restrict__ map) {
    int r = blockIdx.x * 256 + threadIdx.x;
    if (r >= MROWS) return;
    int w = r / NTOK, t = r % NTOK;
    int b = w / NWIN, wrem = w % NWIN;
    int wi = wrem / 8, wj = wrem % 8;
    int ti = t / WS, tj = t % WS;
    int h0 = (wi * WS + ti + 3) % HW;
    int w0 = (wj * WS + tj + 3) % HW;
    map[r] = b * (HW * HW) + h0 * HW + w0;
}

// ---------------- conversions ----------------
__device__ __forceinline__ void split_fp16(float v, __half& h, __half& l) {
    h = __float2half(v);
    l = __float2half(v - __half2float(h));
}

#define S_QKV (3 * CH * CH)
#define S_PRJ (CH * CH)
#define S_FC1 (HID * CH)
#define S_FC2 (CH * HID)
#define S_ALL (S_QKV + S_PRJ + S_FC1 + S_FC2)

__global__ void conv_wsplit_all(
    const float* __restrict__ w0, __half* __restrict__ h0, __half* __restrict__ l0,
    const float* __restrict__ w1, __half* __restrict__ h1, __half* __restrict__ l1,
    const float* __restrict__ w2, __half* __restrict__ h2, __half* __restrict__ l2,
    const float* __restrict__ w3, __half* __restrict__ h3, __half* __restrict__ l3)
{
    long i = (long)blockIdx.x * 256 + threadIdx.x;
    if (i >= S_ALL) return;
    const float* src; __half *hi, *lo; long j = i;
    if (j < S_QKV)                 { src = w0; hi = h0; lo = l0; }
    else if ((j -= S_QKV) < S_PRJ) { src = w1; hi = h1; lo = l1; }
    else if ((j -= S_PRJ) < S_FC1) { src = w2; hi = h2; lo = l2; }
    else { j -= S_FC1;               src = w3; hi = h3; lo = l3; }
    __half h, l;
    split_fp16(src[j], h, l);
    hi[j] = h; lo[j] = l;
}

__global__ void conv_gather(const float* __restrict__ x, const int* __restrict__ map,
                            __half* __restrict__ o) {
    long i = (long)blockIdx.x * 256 + threadIdx.x;
    if (i >= (long)MROWS * CH) return;
    long r = i / CH, c = i % CH;
    o[i] = __float2half(x[(long)map[r] * CH + c]);
}

// ---------------- pipelined fp16x2 HMMA GEMM ------------------------------
// C[M,N] = A[M,K] @ (Wh+Wl)[N,K]^T + bias.  CTA tile 128x128 x BK32,
// 3-stage cp.async, 256 threads / 8 warps, 2 CTAs/SM.
// Mainloop issues all 8 hi-product HMMAs (distinct accumulators) before the
// 8 lo-products -> no back-to-back accumulator RAW.
// EPI: 0 fp16 out, 1 fp32 scatter via c_map, 2 GELU->fp16, 3 +resid fp32.

#define RSTRIDE 80
#define TILE_B  (128 * RSTRIDE)            // 10240
#define STAGE_B (3 * TILE_B)               // A, Bh, Bl = 30720
#define STAGES  3
#define SMEM_REQ (STAGES * STAGE_B)        // 92160 -> 2 CTAs/SM

__device__ __forceinline__ void load_stage(
    uint32_t sbase, const __half* A, const __half* Bh, const __half* Bl,
    int K, int k0, int tid)
{
    int row = tid >> 1;
    int c0 = (tid & 1) * 32;
    uint32_t so = (uint32_t)(row * RSTRIDE + c0);
    size_t go = (size_t)row * K + k0;
    const char* pa = (const char*)(A + go) + c0;
    const char* pb = (const char*)(Bh + go) + c0;
    const char* pc = (const char*)(Bl + go) + c0;
    CP16(sbase + so,                    pa);
    CP16(sbase + so + 16,               pa + 16);
    CP16(sbase + TILE_B + so,           pb);
    CP16(sbase + TILE_B + so + 16,      pb + 16);
    CP16(sbase + 2 * TILE_B + so,       pc);
    CP16(sbase + 2 * TILE_B + so + 16,  pc + 16);
}

template <int EPI>
__global__ __launch_bounds__(256, 2)
void gemm_mma(const __half* __restrict__ A,
              const __half* __restrict__ Bhw, const __half* __restrict__ Blw,
              const float* __restrict__ bias,
              float* __restrict__ Cf, __half* __restrict__ Ch,
              int M, int N, int K,
              const int* __restrict__ c_map, const float* __restrict__ resid)
{
    extern __shared__ char smem[];
    uint32_t sb = smem_u32(smem);

    int tid = threadIdx.x;
    int wid = tid >> 5, lane = tid & 31;
    int warpM = wid & 1, warpN = wid >> 1;
    int bm = blockIdx.y * 128, bn = blockIdx.x * 128;
    int grp = lane >> 2, tig = lane & 3;

    const __half* pA  = A   + (size_t)bm * K;
    const __half* pBh = Bhw + (size_t)bn * K;
    const __half* pBl = Blw + (size_t)bn * K;

    int a_row = warpM * 64 + (lane & 7) + ((lane >> 3) & 1) * 8;
    uint32_t a_off = (uint32_t)(a_row * RSTRIDE + (lane >> 4) * 16);
    int b_row = warpN * 32 + (lane & 7) + (lane >> 4) * 8;
    uint32_t b_off = (uint32_t)(b_row * RSTRIDE + ((lane >> 3) & 1) * 16);

    float acc[4][4][4];
    #pragma unroll
    for (int a = 0; a < 4; a++)
        #pragma unroll
        for (int b = 0; b < 4; b++)
            #pragma unroll
            for (int c = 0; c < 4; c++) acc[a][b][c] = 0.0f;

    int nk = K / 32;

    load_stage(sb, pA, pBh, pBl, K, 0, tid);
    CP_COMMIT();
    load_stage(sb + STAGE_B, pA, pBh, pBl, K, 32, tid);
    CP_COMMIT();

    for (int k = 0; k < nk; k++) {
        CP_WAIT(1);
        __syncthreads();

        int kp = k + 2;
        if (kp < nk)
            load_stage(sb + (kp % STAGES) * STAGE_B, pA, pBh, pBl, K, kp * 32, tid);
        CP_COMMIT();

        uint32_t st = sb + (k % STAGES) * STAGE_B;
        uint32_t sA = st, sBh = st + TILE_B, sBl = st + 2 * TILE_B;

        #pragma unroll
        for (int ks = 0; ks < 2; ks++) {
            uint32_t ko = ks * 32;
            uint32_t af[4][4], bh[2][4], bl[2][4];
            #pragma unroll
            for (int mf = 0; mf < 4; mf++)
                ldsm4(af[mf], sA + a_off + (uint32_t)(mf * 16 * RSTRIDE) + ko);
            #pragma unroll
            for (int nfp = 0; nfp < 2; nfp++) {
                ldsm4(bh[nfp], sBh + b_off + (uint32_t)(nfp * 16 * RSTRIDE) + ko);
                ldsm4(bl[nfp], sBl + b_off + (uint32_t)(nfp * 16 * RSTRIDE) + ko);
            }
            // pass 1: hi products -- 16 HMMAs, all distinct accumulators
            #pragma unroll
            for (int nfp = 0; nfp < 2; nfp++)
                #pragma unroll
                for (int mf = 0; mf < 4; mf++) {
                    mma16816(acc[mf][2 * nfp],     af[mf], bh[nfp][0], bh[nfp][1]);
                    mma16816(acc[mf][2 * nfp + 1], af[mf], bh[nfp][2], bh[nfp][3]);
                }
            // pass 2: lo products -- dependent writes now 15 HMMAs apart
            #pragma unroll
            for (int nfp = 0; nfp < 2; nfp++)
                #pragma unroll
                for (int mf = 0; mf < 4; mf++) {
                    mma16816(acc[mf][2 * nfp],     af[mf], bl[nfp][0], bl[nfp][1]);
                    mma16816(acc[mf][2 * nfp + 1], af[mf], bl[nfp][2], bl[nfp][3]);
                }
        }
        __syncthreads();
    }

    // epilogue: warp covers rows [warpM*64, +64), cols [warpN*32, +32)
    #pragma unroll
    for (int mf = 0; mf < 4; mf++) {
        int mbase = bm + warpM * 64 + mf * 16 + grp;
        #pragma unroll
        for (int nf = 0; nf < 4; nf++) {
            int n0 = bn + warpN * 32 + nf * 8 + 2 * tig;
            float bi0 = bias[n0], bi1 = bias[n0 + 1];
            #pragma unroll
            for (int half_ = 0; half_ < 2; half_++) {
                int m = mbase + half_ * 8;
                float v0 = acc[mf][nf][half_ * 2 + 0] + bi0;
                float v1 = acc[mf][nf][half_ * 2 + 1] + bi1;
                if (EPI == 0) {
                    __half2 hp;
                    hp.x = __float2half(v0); hp.y = __float2half(v1);
                    *(__half2*)(Ch + (size_t)m * N + n0) = hp;
                } else if (EPI == 1) {
                    size_t orow = (size_t)c_map[m];
                    Cf[orow * N + n0]     = v0;
                    Cf[orow * N + n0 + 1] = v1;
                } else if (EPI == 2) {
                    v0 = 0.5f * v0 * (1.0f + erff(v0 * 0.70710678118654752f));
                    v1 = 0.5f * v1 * (1.0f + erff(v1 * 0.70710678118654752f));
                    __half2 hp;
                    hp.x = __float2half(v0); hp.y = __float2half(v1);
                    *(__half2*)(Ch + (size_t)m * N + n0) = hp;
                } else {
                    size_t rb = (size_t)m * N + n0;
                    Cf[rb]     = v0 + resid[rb];
                    Cf[rb + 1] = v1 + resid[rb + 1];
                }
            }
        }
    }
}

// ---------------- windowed attention (fp16 in/out, parallel softmax) -------
__global__ __launch_bounds__(256)
void attn_kernel(const __half* __restrict__ qkv, const float* __restrict__ mask,
                 const float* __restrict__ rpb, __half* __restrict__ o)
{
    int w = blockIdx.x;
    int h = blockIdx.y;

    __shared__ float q[NTOK][HD];
    __shared__ float k[NTOK][HD];
    __shared__ float v[NTOK][HD];
    __shared__ float s[NTOK][52];

    int tid = threadIdx.x;
    int wid = tid >> 5, lane = tid & 31;
    const __half* base = qkv + (long)w * NTOK * (3 * CH) + h * HD;

    for (int idx = tid; idx < NTOK * (HD / 2); idx += 256) {
        int t = idx >> 4, d2 = idx & 15;
        const __half2* row = (const __half2*)(base + (long)t * (3 * CH)) + d2;
        float2 qv = __half22float2(row[0]);
        float2 kv = __half22float2(row[CH / 2]);
        float2 vv = __half22float2(row[CH]);
        q[t][d2 * 2]     = qv.x * SCALE;
        q[t][d2 * 2 + 1] = qv.y * SCALE;
        k[t][d2 * 2]     = kv.x;
        k[t][d2 * 2 + 1] = kv.y;
        v[t][d2 * 2]     = vv.x;
        v[t][d2 * 2 + 1] = vv.y;
    }
    __syncthreads();

    int wimg = w & (NWIN - 1);
    const float* mrow = mask + (long)wimg * NTOK * NTOK;
    for (int idx = tid; idx < NTOK * NTOK; idx += 256) {
        int t1 = idx / NTOK, t2 = idx % NTOK;
        float acc = 0.0f;
        #pragma unroll
        for (int d = 0; d < HD; d++) acc += q[t1][d] * k[t2][d];
        int di = (t1 / WS) - (t2 / WS) + (WS - 1);
        int dj = (t1 % WS) - (t2 % WS) + (WS - 1);
        acc += rpb[(di * (2 * WS - 1) + dj) * NHEAD + h];
        acc += mrow[idx];
        s[t1][t2] = acc;
    }
    __syncthreads();

    for (int row = wid; row < NTOK; row += 8) {
        float e0 = s[row][lane];
        bool has1 = (lane + 32) < NTOK;
        float e1 = has1 ? s[row][lane + 32] : -1e30f;
        float mx = fmaxf(e0, e1);
        #pragma unroll
        for (int off = 16; off; off >>= 1)
            mx = fmaxf(mx, __shfl_xor_sync(0xffffffff, mx, off));
        float x0 = __expf(e0 - mx);
        float x1 = has1 ? __expf(e1 - mx) : 0.0f;
        float sm = x0 + x1;
        #pragma unroll
        for (int off = 16; off; off >>= 1)
            sm += __shfl_xor_sync(0xffffffff, sm, off);
        float inv = 1.0f / sm;
        s[row][lane] = x0 * inv;
        if (has1) s[row][lane + 32] = x1 * inv;
    }
    __syncthreads();

    __half* ob = o + (long)w * NTOK * CH + h * HD;
    for (int idx = tid; idx < NTOK * (HD / 2); idx += 256) {
        int t = idx >> 4, d2 = idx & 15;
        int d = d2 * 2;
        float a0 = 0.0f, a1 = 0.0f;
        #pragma unroll
        for (int m = 0; m < NTOK; m++) {
            float sm = s[t][m];
            a0 += sm * v[m][d];
            a1 += sm * v[m][d + 1];
        }
        __half2 hp;
        hp.x = __float2half(a0); hp.y = __float2half(a1);
        *(__half2*)(ob + (long)t * CH + d) = hp;
    }
}

// ---------------- LayerNorm -> fp16 ----------------
__global__ __launch_bounds__(128)
void ln_kernel(const float* __restrict__ x, const float* __restrict__ g,
               const float* __restrict__ b, __half* __restrict__ o)
{
    long row = blockIdx.x;
    const float* xr = x + row * CH;
    int tid = threadIdx.x;

    float v0 = xr[tid], v1 = xr[tid + 128], v2 = xr[tid + 256];
    float sum = v0 + v1 + v2;

    __shared__ float red1[4];
    __shared__ float red2[4];
    #pragma unroll
    for (int off = 16; off; off >>= 1) sum += __shfl_xor_sync(0xffffffff, sum, off);
    if ((tid & 31) == 0) red1[tid >> 5] = sum;
    __syncthreads();
    float mu = (red1[0] + red1[1] + red1[2] + red1[3]) * (1.0f / CH);

    float d0 = v0 - mu, d1 = v1 - mu, d2 = v2 - mu;
    float sq = d0 * d0 + d1 * d1 + d2 * d2;
    #pragma unroll
    for (int off = 16; off; off >>= 1) sq += __shfl_xor_sync(0xffffffff, sq, off);
    if ((tid & 31) == 0) red2[tid >> 5] = sq;
    __syncthreads();
    float var = (red2[0] + red2[1] + red2[2] + red2[3]) * (1.0f / CH);
    float rstd = rsqrtf(var + 1e-5f);

    long base = row * CH;
    o[base + tid]       = __float2half(d0 * rstd * g[tid]       + b[tid]);
    o[base + tid + 128] = __float2half(d1 * rstd * g[tid + 128] + b[tid + 128]);
    o[base + tid + 256] = __float2half(d2 * rstd * g[tid + 256] + b[tid + 256]);
}

// ---------------- launch ----------------
extern "C" void kernel_launch(void* const* d_in, const int* in_sizes, int n_in,
                              void* d_out, int out_size)
{
    const float* x      = (const float*)d_in[0];
    const float* mask   = (const float*)d_in[1];
    const float* qkv_w  = (const float*)d_in[2];
    const float* qkv_b  = (const float*)d_in[3];
    const float* proj_w = (const float*)d_in[4];
    const float* proj_b = (const float*)d_in[5];
    const float* rpb    = (const float*)d_in[6];
    const float* n2g    = (const float*)d_in[7];
    const float* n2b    = (const float*)d_in[8];
    const float* fc1w   = (const float*)d_in[9];
    const float* fc1b   = (const float*)d_in[10];
    const float* fc2w   = (const float*)d_in[11];
    const float* fc2b   = (const float*)d_in[12];
    float* out = (float*)d_out;

    void *p;
    #define GSYM(sym, var, ty) cudaGetSymbolAddress(&p, sym); ty* var = (ty*)p;
    GSYM(g_xg, xg, __half)
    GSYM(g_qkv, qkv, __half)
    GSYM(g_at, at, __half)
    GSYM(g_x2, x2, float)
    GSYM(g_hn, hn, __half)
    GSYM(g_hid, hid, __half)
    GSYM(g_map, map, int)
    GSYM(g_wqkv_hi, wqkv_hi, __half) GSYM(g_wqkv_lo, wqkv_lo, __half)
    GSYM(g_wprj_hi, wprj_hi, __half) GSYM(g_wprj_lo, wprj_lo, __half)
    GSYM(g_wf1_hi, wf1_hi, __half) GSYM(g_wf1_lo, wf1_lo, __half)
    GSYM(g_wf2_hi, wf2_hi, __half) GSYM(g_wf2_lo, wf2_lo, __half)
    #undef GSYM

    cudaFuncSetAttribute(gemm_mma<0>, cudaFuncAttributeMaxDynamicSharedMemorySize, SMEM_REQ);
    cudaFuncSetAttribute(gemm_mma<1>, cudaFuncAttributeMaxDynamicSharedMemorySize, SMEM_REQ);
    cudaFuncSetAttribute(gemm_mma<2>, cudaFuncAttributeMaxDynamicSharedMemorySize, SMEM_REQ);
    cudaFuncSetAttribute(gemm_mma<3>, cudaFuncAttributeMaxDynamicSharedMemorySize, SMEM_REQ);

    build_maps_kernel<<<(MROWS + 255) / 256, 256>>>(map);

    long nx = (long)MROWS * CH;
    conv_gather<<<(int)((nx + 255) / 256), 256>>>(x, map, xg);
    conv_wsplit_all<<<(S_ALL + 255) / 256, 256>>>(
        qkv_w, wqkv_hi, wqkv_lo, proj_w, wprj_hi, wprj_lo,
        fc1w, wf1_hi, wf1_lo, fc2w, wf2_hi, wf2_lo);

    // QKV -> fp16 qkv (windowed order)
    gemm_mma<0><<<dim3((3 * CH) / 128, MROWS / 128), 256, SMEM_REQ>>>(
        xg, wqkv_hi, wqkv_lo, qkv_b, nullptr, qkv,
        MROWS, 3 * CH, CH, nullptr, nullptr);

    attn_kernel<<<dim3(BATCH * NWIN, NHEAD), 256>>>(qkv, mask, rpb, at);

    // proj + scatter to image order -> x2 (fp32)
    gemm_mma<1><<<dim3(CH / 128, MROWS / 128), 256, SMEM_REQ>>>(
        at, wprj_hi, wprj_lo, proj_b, x2, nullptr,
        MROWS, CH, CH, map, nullptr);

    ln_kernel<<<MROWS, 128>>>(x2, n2g, n2b, hn);

    // FC1 + GELU -> fp16
    gemm_mma<2><<<dim3(HID / 128, MROWS / 128), 256, SMEM_REQ>>>(
        hn, wf1_hi, wf1_lo, fc1b, nullptr, hid,
        MROWS, HID, CH, nullptr, nullptr);

    // FC2 + residual -> out (fp32)
    gemm_mma<3><<<dim3(CH / 128, MROWS / 128), 256, SMEM_REQ>>>(
        hid, wf2_hi, wf2_lo, fc2b, out, nullptr,
        MROWS, CH, HID, nullptr, x2);
}